// round 6
// baseline (speedup 1.0000x reference)
#include <cuda_runtime.h>
#include <cuda_bf16.h>
#include <cstdint>

#define NCLS 64
#define DIM 256
#define NROWS 65536
#define TOTROWS 131072

__device__ __align__(16) __nv_bfloat16 g_featbf[(size_t)TOTROWS * DIM];
__device__ float  g_scratch[2 * 256 * NCLS * 256];     // [feat][chunk][cls][col] 32MB
__device__ float  g_wsum4[4 * 32768];
__device__ int    g_icnt[2][NCLS];
__device__ __align__(16) __nv_bfloat16 g_wbf[4 * 8192];  // W bf16 pre-swizzled
__device__ float  g_inv[3 * NCLS];
__device__ double g_acc;
__device__ int    g_lstride;

__device__ __forceinline__ uint32_t smem_u32(const void* p) {
    uint32_t r;
    asm("{ .reg .u64 t; cvta.to.shared.u64 t, %1; cvt.u32.u64 %0, t; }" : "=r"(r) : "l"(p));
    return r;
}
__device__ __forceinline__ void cpa16(uint32_t dst, const void* src) {
    asm volatile("cp.async.cg.shared.global [%0], [%1], 16;" :: "r"(dst), "l"(src));
}
__device__ __forceinline__ void cp_commit() { asm volatile("cp.async.commit_group;"); }
template<int N> __device__ __forceinline__ void cp_wait() {
    asm volatile("cp.async.wait_group %0;" :: "n"(N));
}
__device__ __forceinline__ uint32_t lds_u32(uint32_t a) {
    uint32_t v; asm volatile("ld.shared.b32 %0, [%1];" : "=r"(v) : "r"(a)); return v;
}
__device__ __forceinline__ void mma_bf16(float* d, const uint32_t* a, const uint32_t* b) {
    asm volatile("mma.sync.aligned.m16n8k16.row.col.f32.bf16.bf16.f32 "
        "{%0,%1,%2,%3}, {%4,%5,%6,%7}, {%8,%9}, {%0,%1,%2,%3};"
        : "+f"(d[0]), "+f"(d[1]), "+f"(d[2]), "+f"(d[3])
        : "r"(a[0]), "r"(a[1]), "r"(a[2]), "r"(a[3]), "r"(b[0]), "r"(b[1]));
}
__device__ __forceinline__ float qmax(float v) {
    v = fmaxf(v, __shfl_xor_sync(~0u, v, 1));
    v = fmaxf(v, __shfl_xor_sync(~0u, v, 2));
    return v;
}
__device__ __forceinline__ float qsum(float v) {
    v += __shfl_xor_sync(~0u, v, 1);
    v += __shfl_xor_sync(~0u, v, 2);
    return v;
}

__global__ void k_detect(const int* __restrict__ lbl) {
    bool oz = true;
    #pragma unroll
    for (int i = 0; i < 64; ++i) oz &= (lbl[2 * i + 1] == 0);
    g_lstride = oz ? 2 : 1;
}

__global__ void k_zero() {
    int i = threadIdx.x;
    if (i < 128) ((int*)g_icnt)[i] = 0;
    if (i == 128) g_acc = 0.0;
}

__global__ void __launch_bounds__(256) k_hist(const int* __restrict__ sl,
                                              const int* __restrict__ tl) {
    __shared__ int h[NCLS];
    const int feat = blockIdx.x >> 5;
    const int* lp = feat ? tl : sl;
    const int ls = g_lstride, tid = threadIdx.x;
    if (tid < NCLS) h[tid] = 0;
    __syncthreads();
    const int base = (blockIdx.x & 31) * 2048;
    #pragma unroll
    for (int i = 0; i < 8; ++i)
        atomicAdd(&h[lp[(base + tid + i * 256) * ls] & 63], 1);
    __syncthreads();
    if (tid < NCLS) atomicAdd(&g_icnt[feat][tid], h[tid]);
}

// ---- segment sums: 512 blocks (2 feat x 256 chunks of 256 rows), 128 thr ----
// thread owns 2 cols (float2); 16-row batches -> 4KB in flight per warp
__global__ void __launch_bounds__(128) k_segsum(const float* __restrict__ src,
        const float* __restrict__ trg, const int* __restrict__ sl,
        const int* __restrict__ tl) {
    extern __shared__ float2 bins[];           // [64][128] float2 = 64KB
    __shared__ int lbl_s[256];
    const int feat = blockIdx.x >> 8, chunk = blockIdx.x & 255;
    const float* fp = feat ? trg : src;
    const int*   lp = feat ? tl : sl;
    const int ls = g_lstride, tid = threadIdx.x;
    const int base = chunk * 256;

    lbl_s[tid]       = lp[(base + tid) * ls] & 63;
    lbl_s[tid + 128] = lp[(base + tid + 128) * ls] & 63;
    #pragma unroll
    for (int c = 0; c < NCLS; ++c) bins[c * 128 + tid] = make_float2(0.f, 0.f);
    __syncthreads();

    const float2* fin = (const float2*)fp + (size_t)base * 128 + tid;
    __nv_bfloat162* outb = (__nv_bfloat162*)g_featbf
                         + (size_t)(feat * NROWS + base) * 128 + tid;

    for (int r0 = 0; r0 < 256; r0 += 16) {
        int cc[16]; float2 ff[16];
        #pragma unroll
        for (int i = 0; i < 16; ++i) ff[i] = fin[(size_t)(r0 + i) * 128];
        #pragma unroll
        for (int i = 0; i < 16; ++i) cc[i] = lbl_s[r0 + i];
        #pragma unroll
        for (int i = 0; i < 16; ++i)
            outb[(size_t)(r0 + i) * 128] = __floats2bfloat162_rn(ff[i].x, ff[i].y);
        #pragma unroll
        for (int i = 0; i < 16; ++i) {
            float2 b = bins[cc[i] * 128 + tid];
            b.x += ff[i].x; b.y += ff[i].y;
            bins[cc[i] * 128 + tid] = b;
        }
    }
    // each thread owns its column pair: no sync needed
    float2* sc = (float2*)g_scratch + ((size_t)(feat * 256 + chunk) * NCLS) * 128 + tid;
    #pragma unroll 8
    for (int c = 0; c < NCLS; ++c) sc[c * 128] = bins[c * 128 + tid];
}

// ---- reduce stage 1: 4 quarters x 64 chunks each ----
__global__ void __launch_bounds__(512) k_red() {
    int q = blockIdx.x * 512 + threadIdx.x;    // 0..131071
    int quarter = q >> 15, elem = q & 32767;
    int cls = elem >> 8, k = elem & 255;
    int feat = cls >> 6, c = cls & 63;
    const float* p = g_scratch
        + ((size_t)(feat * 256 + quarter * 64) * NCLS + c) * 256 + k;
    float s = 0.f;
    #pragma unroll 8
    for (int ch = 0; ch < 64; ++ch) s += p[(size_t)ch * (NCLS * 256)];
    g_wsum4[quarter * 32768 + elem] = s;
}

// ---- reduce stage 2: combine, swizzle to bf16 W, build inv ----
__global__ void __launch_bounds__(512) k_prep() {
    int idx = blockIdx.x * 512 + threadIdx.x;  // 0..32767
    float s = g_wsum4[idx] + g_wsum4[32768 + idx]
            + g_wsum4[65536 + idx] + g_wsum4[98304 + idx];
    int cls = idx >> 8, k = idx & 255;
    int kc = k >> 6, u = (k >> 3) & 7, e = k & 7;
    int phys = cls * 8 + (u ^ (cls & 7));
    g_wbf[kc * 8192 + phys * 8 + e] = __float2bfloat16(s);
    if (idx < 3 * NCLS) {
        int which = idx >> 6, c2 = idx & 63;
        float cs = (float)g_icnt[0][c2], ct = (float)g_icnt[1][c2];
        g_inv[idx] = (which == 0) ? 1.f / cs : (which == 1) ? 1.f / ct : 1.f / (cs + ct);
    }
}

// ---- fused bf16 GEMM + softmax/KL: 1024 blocks x 256 thr (8 warps) ----
// block: 128 rows x 128 classes; warp: m16 x n128; 2 blocks/SM
#define FS_OFF 65536
#define FS_SZ  16384
#define INV_OFF (FS_OFF + 2 * FS_SZ)
#define RED_OFF (INV_OFF + 768)
#define SMEM_MAIN (RED_OFF + 64)

__global__ void __launch_bounds__(256, 2) k_main() {
    extern __shared__ unsigned char sm[];
    float* inv_s = (float*)(sm + INV_OFF);
    float* red   = (float*)(sm + RED_OFF);
    const uint32_t sb = smem_u32(sm);
    const int tid = threadIdx.x, w = tid >> 5, lane = tid & 31;
    const int g = lane >> 2, t = lane & 3;

    #pragma unroll
    for (int j = 0; j < 16; ++j) {                 // W: 4096 16B units
        int uu = j * 256 + tid;
        cpa16(sb + uu * 16, g_wbf + uu * 8);
    }
    if (tid < 192) inv_s[tid] = g_inv[tid];

    const __nv_bfloat16* frow = g_featbf + (size_t)blockIdx.x * 128 * DIM;
    #pragma unroll
    for (int j = 0; j < 4; ++j) {                  // F chunk 0: 1024 units
        int uu = j * 256 + tid, row = uu >> 3, u = uu & 7;
        cpa16(sb + FS_OFF + (uint32_t)(row * 8 + (u ^ (row & 7))) * 16,
              frow + (size_t)row * DIM + u * 8);
    }
    cp_commit();

    float acc[16][4];
    #pragma unroll
    for (int y = 0; y < 16; ++y)
        #pragma unroll
        for (int z = 0; z < 4; ++z) acc[y][z] = 0.f;

    #pragma unroll
    for (int kc = 0; kc < 4; ++kc) {
        if (kc < 3) {
            #pragma unroll
            for (int j = 0; j < 4; ++j) {
                int uu = j * 256 + tid, row = uu >> 3, u = uu & 7;
                cpa16(sb + FS_OFF + ((kc + 1) & 1) * FS_SZ
                          + (uint32_t)(row * 8 + (u ^ (row & 7))) * 16,
                      frow + (size_t)row * DIM + (kc + 1) * 64 + u * 8);
            }
            cp_commit();
            cp_wait<1>();
        } else {
            cp_wait<0>();
        }
        __syncthreads();

        const uint32_t fb = sb + FS_OFF + (kc & 1) * FS_SZ;
        const uint32_t wb = sb + kc * 16384;
        #pragma unroll
        for (int s = 0; s < 4; ++s) {
            uint32_t a[4];
            int r0 = w * 16 + g, r1 = r0 + 8;
            a[0] = lds_u32(fb + (uint32_t)(r0 * 8 + ((2*s)   ^ (r0 & 7))) * 16 + 4 * t);
            a[1] = lds_u32(fb + (uint32_t)(r1 * 8 + ((2*s)   ^ (r1 & 7))) * 16 + 4 * t);
            a[2] = lds_u32(fb + (uint32_t)(r0 * 8 + ((2*s+1) ^ (r0 & 7))) * 16 + 4 * t);
            a[3] = lds_u32(fb + (uint32_t)(r1 * 8 + ((2*s+1) ^ (r1 & 7))) * 16 + 4 * t);
            #pragma unroll
            for (int nt = 0; nt < 16; ++nt) {
                int cn = nt * 8 + g;
                uint32_t b[2];
                b[0] = lds_u32(wb + (uint32_t)(cn * 8 + ((2*s)   ^ (cn & 7))) * 16 + 4 * t);
                b[1] = lds_u32(wb + (uint32_t)(cn * 8 + ((2*s+1) ^ (cn & 7))) * 16 + 4 * t);
                mma_bf16(acc[nt], a, b);
            }
        }
        __syncthreads();
    }

    float Jtot = 0.f;
    #pragma unroll
    for (int h = 0; h < 2; ++h) {                  // rows g / g+8
        int j0 = h * 2;
        float mS = -1e30f, mT = -1e30f, mM = -1e30f;
        #pragma unroll
        for (int i = 0; i < 16; ++i) {
            int n = i >> 1, j = i & 1, c = n * 8 + 2 * t + j;
            float Sv = acc[n][j0 + j], Tv = acc[n + 8][j0 + j];
            mS = fmaxf(mS, Sv * inv_s[c]);
            mT = fmaxf(mT, Tv * inv_s[64 + c]);
            mM = fmaxf(mM, (Sv + Tv) * inv_s[128 + c]);
        }
        mS = qmax(mS); mT = qmax(mT); mM = qmax(mM);
        float zS = 0.f, zT = 0.f, zM = 0.f;
        #pragma unroll
        for (int i = 0; i < 16; ++i) {
            int n = i >> 1, j = i & 1, c = n * 8 + 2 * t + j;
            float Sv = acc[n][j0 + j], Tv = acc[n + 8][j0 + j];
            zS += __expf(Sv * inv_s[c] - mS);
            zT += __expf(Tv * inv_s[64 + c] - mT);
            zM += __expf((Sv + Tv) * inv_s[128 + c] - mM);
        }
        zS = qsum(zS); zT = qsum(zT); zM = qsum(zM);
        float lseS = mS + __logf(zS), lseT = mT + __logf(zT), lseM = mM + __logf(zM);
        float J = 0.f;
        #pragma unroll
        for (int i = 0; i < 16; ++i) {
            int n = i >> 1, j = i & 1, c = n * 8 + 2 * t + j;
            float Sv = acc[n][j0 + j], Tv = acc[n + 8][j0 + j];
            float ls = Sv * inv_s[c] - lseS;
            float lt = Tv * inv_s[64 + c] - lseT;
            float lm = (Sv + Tv) * inv_s[128 + c] - lseM;
            float es = __expf(ls), et = __expf(lt), em = __expf(lm);
            J += (et - es) * (lt - ls) + (em - es) * (lm - ls) + (em - et) * (lm - lt);
        }
        Jtot += qsum(J);
    }
    Jtot += __shfl_xor_sync(~0u, Jtot, 4);
    Jtot += __shfl_xor_sync(~0u, Jtot, 8);
    Jtot += __shfl_xor_sync(~0u, Jtot, 16);
    if (lane == 0) red[w] = Jtot;
    __syncthreads();
    if (tid == 0) {
        float bs = 0.f;
        #pragma unroll
        for (int i = 0; i < 8; ++i) bs += red[i];
        atomicAdd(&g_acc, (double)bs);
    }
}

__global__ void k_final(float* out) {
    out[0] = (float)(g_acc * (0.5 / (3.0 * 131072.0 * 64.0)));
}

extern "C" void kernel_launch(void* const* d_in, const int* in_sizes, int n_in,
                              void* d_out, int out_size) {
    const float* src = (const float*)d_in[0];
    const float* trg = (const float*)d_in[1];
    const int*   sl  = (const int*)d_in[2];
    const int*   tl  = (const int*)d_in[3];

    cudaFuncSetAttribute(k_segsum, cudaFuncAttributeMaxDynamicSharedMemorySize, 65536);
    cudaFuncSetAttribute(k_main,   cudaFuncAttributeMaxDynamicSharedMemorySize, SMEM_MAIN);

    k_detect<<<1, 1>>>(sl);
    k_zero<<<1, 256>>>();
    k_hist<<<64, 256>>>(sl, tl);
    k_segsum<<<512, 128, 65536>>>(src, trg, sl, tl);
    k_red<<<256, 512>>>();
    k_prep<<<64, 512>>>();
    k_main<<<1024, 256, SMEM_MAIN>>>();
    k_final<<<1, 1>>>((float*)d_out);
}

// round 7
// speedup vs baseline: 2.3750x; 2.3750x over previous
#include <cuda_runtime.h>
#include <cuda_bf16.h>
#include <cstdint>

#define NCLS 64
#define DIM 256
#define NROWS 65536
#define TOTROWS 131072

__device__ __align__(16) __nv_bfloat16 g_featbf[(size_t)TOTROWS * DIM];
__device__ float  g_scratch[2 * 256 * NCLS * 256];     // [feat][chunk][cls][col] 32MB
__device__ float  g_wsum4[4 * 32768];
__device__ int    g_icnt[2][NCLS];
__device__ __align__(16) __nv_bfloat16 g_wbf[4 * 8192];  // W bf16 pre-swizzled
__device__ float  g_inv[3 * NCLS];
__device__ double g_acc;
__device__ int    g_lstride;

__device__ __forceinline__ uint32_t smem_u32(const void* p) {
    uint32_t r;
    asm("{ .reg .u64 t; cvta.to.shared.u64 t, %1; cvt.u32.u64 %0, t; }" : "=r"(r) : "l"(p));
    return r;
}
__device__ __forceinline__ void cpa16(uint32_t dst, const void* src) {
    asm volatile("cp.async.cg.shared.global [%0], [%1], 16;" :: "r"(dst), "l"(src));
}
__device__ __forceinline__ void cp_commit() { asm volatile("cp.async.commit_group;"); }
template<int N> __device__ __forceinline__ void cp_wait() {
    asm volatile("cp.async.wait_group %0;" :: "n"(N));
}
__device__ __forceinline__ uint32_t lds_u32(uint32_t a) {
    uint32_t v; asm volatile("ld.shared.b32 %0, [%1];" : "=r"(v) : "r"(a)); return v;
}
__device__ __forceinline__ void mma_bf16(float* d, const uint32_t* a, const uint32_t* b) {
    asm volatile("mma.sync.aligned.m16n8k16.row.col.f32.bf16.bf16.f32 "
        "{%0,%1,%2,%3}, {%4,%5,%6,%7}, {%8,%9}, {%0,%1,%2,%3};"
        : "+f"(d[0]), "+f"(d[1]), "+f"(d[2]), "+f"(d[3])
        : "r"(a[0]), "r"(a[1]), "r"(a[2]), "r"(a[3]), "r"(b[0]), "r"(b[1]));
}
__device__ __forceinline__ float qmax(float v) {
    v = fmaxf(v, __shfl_xor_sync(~0u, v, 1));
    v = fmaxf(v, __shfl_xor_sync(~0u, v, 2));
    return v;
}
__device__ __forceinline__ float qsum(float v) {
    v += __shfl_xor_sync(~0u, v, 1);
    v += __shfl_xor_sync(~0u, v, 2);
    return v;
}

__global__ void k_detect(const int* __restrict__ lbl) {
    bool oz = true;
    #pragma unroll
    for (int i = 0; i < 64; ++i) oz &= (lbl[2 * i + 1] == 0);
    g_lstride = oz ? 2 : 1;
}

__global__ void k_zero() {
    int i = threadIdx.x;
    if (i < 128) ((int*)g_icnt)[i] = 0;
    if (i == 128) g_acc = 0.0;
}

__global__ void __launch_bounds__(256) k_hist(const int* __restrict__ sl,
                                              const int* __restrict__ tl) {
    __shared__ int h[NCLS];
    const int feat = blockIdx.x >> 5;
    const int* lp = feat ? tl : sl;
    const int ls = g_lstride, tid = threadIdx.x;
    if (tid < NCLS) h[tid] = 0;
    __syncthreads();
    const int base = (blockIdx.x & 31) * 2048;
    #pragma unroll
    for (int i = 0; i < 8; ++i)
        atomicAdd(&h[lp[(base + tid + i * 256) * ls] & 63], 1);
    __syncthreads();
    if (tid < NCLS) atomicAdd(&g_icnt[feat][tid], h[tid]);
}

// ---- segment sums: 512 blocks (2 feat x 256 chunks of 256 rows), 128 thr ----
// feats stream through a 4-stage cp.async smem ring (8 rows = 8KB per stage);
// MLP lives in the async pipeline, not registers.
__global__ void __launch_bounds__(128) k_segsum(const float* __restrict__ src,
        const float* __restrict__ trg, const int* __restrict__ sl,
        const int* __restrict__ tl) {
    extern __shared__ float smf[];             // [4][2048] staging + [64][128] float2 bins
    float2* bins = (float2*)(smf + 4 * 2048);  // 64KB
    __shared__ int lbl_s[256];
    const int feat = blockIdx.x >> 8, chunk = blockIdx.x & 255;
    const float* fp = feat ? trg : src;
    const int*   lp = feat ? tl : sl;
    const int ls = g_lstride, tid = threadIdx.x;
    const int base = chunk * 256;
    const uint32_t sbs = smem_u32(smf);

    const float* fin = fp + (size_t)base * DIM;

    // prologue: stages 0..2 in flight
    #pragma unroll
    for (int s = 0; s < 3; ++s) {
        #pragma unroll
        for (int j = 0; j < 4; ++j) {
            int uu = j * 128 + tid;
            cpa16(sbs + (uint32_t)(s * 8192 + uu * 16), fin + (size_t)s * 2048 + uu * 4);
        }
        cp_commit();
    }

    lbl_s[tid]       = lp[(base + tid) * ls] & 63;
    lbl_s[tid + 128] = lp[(base + tid + 128) * ls] & 63;
    #pragma unroll
    for (int c = 0; c < NCLS; ++c) bins[c * 128 + tid] = make_float2(0.f, 0.f);

    __nv_bfloat162* outb = (__nv_bfloat162*)g_featbf
                         + (size_t)(feat * NROWS + base) * 128 + tid;

    for (int s = 0; s < 32; ++s) {
        if (s + 3 < 32) {
            #pragma unroll
            for (int j = 0; j < 4; ++j) {
                int uu = j * 128 + tid;
                cpa16(sbs + (uint32_t)((((s + 3) & 3) * 8192) + uu * 16),
                      fin + (size_t)(s + 3) * 2048 + uu * 4);
            }
        }
        cp_commit();        // possibly-empty group keeps wait arithmetic exact
        cp_wait<3>();
        __syncthreads();

        const float2* sp = (const float2*)(smf + (s & 3) * 2048);
        #pragma unroll
        for (int i = 0; i < 8; ++i) {
            int r = s * 8 + i;
            float2 v = sp[i * 128 + tid];
            outb[(size_t)r * 128] = __floats2bfloat162_rn(v.x, v.y);
            int c = lbl_s[r];
            float2 b = bins[c * 128 + tid];
            b.x += v.x; b.y += v.y;
            bins[c * 128 + tid] = b;
        }
        __syncthreads();    // stage buffer safe to overwrite next iter
    }

    float2* sc = (float2*)g_scratch + ((size_t)(feat * 256 + chunk) * NCLS) * 128 + tid;
    #pragma unroll 8
    for (int c = 0; c < NCLS; ++c) sc[c * 128] = bins[c * 128 + tid];
}

// ---- reduce stage 1: 4 quarters x 64 chunks each ----
__global__ void __launch_bounds__(512) k_red() {
    int q = blockIdx.x * 512 + threadIdx.x;    // 0..131071
    int quarter = q >> 15, elem = q & 32767;
    int cls = elem >> 8, k = elem & 255;
    int feat = cls >> 6, c = cls & 63;
    const float* p = g_scratch
        + ((size_t)(feat * 256 + quarter * 64) * NCLS + c) * 256 + k;
    float s = 0.f;
    #pragma unroll 8
    for (int ch = 0; ch < 64; ++ch) s += p[(size_t)ch * (NCLS * 256)];
    g_wsum4[quarter * 32768 + elem] = s;
}

// ---- reduce stage 2: combine, swizzle to bf16 W, build inv ----
__global__ void __launch_bounds__(512) k_prep() {
    int idx = blockIdx.x * 512 + threadIdx.x;  // 0..32767
    float s = g_wsum4[idx] + g_wsum4[32768 + idx]
            + g_wsum4[65536 + idx] + g_wsum4[98304 + idx];
    int cls = idx >> 8, k = idx & 255;
    int kc = k >> 6, u = (k >> 3) & 7, e = k & 7;
    int phys = cls * 8 + (u ^ (cls & 7));
    g_wbf[kc * 8192 + phys * 8 + e] = __float2bfloat16(s);
    if (idx < 3 * NCLS) {
        int which = idx >> 6, c2 = idx & 63;
        float cs = (float)g_icnt[0][c2], ct = (float)g_icnt[1][c2];
        g_inv[idx] = (which == 0) ? 1.f / cs : (which == 1) ? 1.f / ct : 1.f / (cs + ct);
    }
}

// ---- fused bf16 GEMM + softmax/KL: 1024 blocks x 256 thr (8 warps) ----
#define FS_OFF 65536
#define FS_SZ  16384
#define INV_OFF (FS_OFF + 2 * FS_SZ)
#define RED_OFF (INV_OFF + 768)
#define SMEM_MAIN (RED_OFF + 64)

__global__ void __launch_bounds__(256, 2) k_main() {
    extern __shared__ unsigned char sm[];
    float* inv_s = (float*)(sm + INV_OFF);
    float* red   = (float*)(sm + RED_OFF);
    const uint32_t sb = smem_u32(sm);
    const int tid = threadIdx.x, w = tid >> 5, lane = tid & 31;
    const int g = lane >> 2, t = lane & 3;

    #pragma unroll
    for (int j = 0; j < 16; ++j) {
        int uu = j * 256 + tid;
        cpa16(sb + uu * 16, g_wbf + uu * 8);
    }
    if (tid < 192) inv_s[tid] = g_inv[tid];

    const __nv_bfloat16* frow = g_featbf + (size_t)blockIdx.x * 128 * DIM;
    #pragma unroll
    for (int j = 0; j < 4; ++j) {
        int uu = j * 256 + tid, row = uu >> 3, u = uu & 7;
        cpa16(sb + FS_OFF + (uint32_t)(row * 8 + (u ^ (row & 7))) * 16,
              frow + (size_t)row * DIM + u * 8);
    }
    cp_commit();

    float acc[16][4];
    #pragma unroll
    for (int y = 0; y < 16; ++y)
        #pragma unroll
        for (int z = 0; z < 4; ++z) acc[y][z] = 0.f;

    #pragma unroll
    for (int kc = 0; kc < 4; ++kc) {
        if (kc < 3) {
            #pragma unroll
            for (int j = 0; j < 4; ++j) {
                int uu = j * 256 + tid, row = uu >> 3, u = uu & 7;
                cpa16(sb + FS_OFF + ((kc + 1) & 1) * FS_SZ
                          + (uint32_t)(row * 8 + (u ^ (row & 7))) * 16,
                      frow + (size_t)row * DIM + (kc + 1) * 64 + u * 8);
            }
            cp_commit();
            cp_wait<1>();
        } else {
            cp_wait<0>();
        }
        __syncthreads();

        const uint32_t fb = sb + FS_OFF + (kc & 1) * FS_SZ;
        const uint32_t wb = sb + kc * 16384;
        #pragma unroll
        for (int s = 0; s < 4; ++s) {
            uint32_t a[4];
            int r0 = w * 16 + g, r1 = r0 + 8;
            a[0] = lds_u32(fb + (uint32_t)(r0 * 8 + ((2*s)   ^ (r0 & 7))) * 16 + 4 * t);
            a[1] = lds_u32(fb + (uint32_t)(r1 * 8 + ((2*s)   ^ (r1 & 7))) * 16 + 4 * t);
            a[2] = lds_u32(fb + (uint32_t)(r0 * 8 + ((2*s+1) ^ (r0 & 7))) * 16 + 4 * t);
            a[3] = lds_u32(fb + (uint32_t)(r1 * 8 + ((2*s+1) ^ (r1 & 7))) * 16 + 4 * t);
            #pragma unroll
            for (int nt = 0; nt < 16; ++nt) {
                int cn = nt * 8 + g;
                uint32_t b[2];
                b[0] = lds_u32(wb + (uint32_t)(cn * 8 + ((2*s)   ^ (cn & 7))) * 16 + 4 * t);
                b[1] = lds_u32(wb + (uint32_t)(cn * 8 + ((2*s+1) ^ (cn & 7))) * 16 + 4 * t);
                mma_bf16(acc[nt], a, b);
            }
        }
        __syncthreads();
    }

    float Jtot = 0.f;
    #pragma unroll
    for (int h = 0; h < 2; ++h) {
        int j0 = h * 2;
        float mS = -1e30f, mT = -1e30f, mM = -1e30f;
        #pragma unroll
        for (int i = 0; i < 16; ++i) {
            int n = i >> 1, j = i & 1, c = n * 8 + 2 * t + j;
            float Sv = acc[n][j0 + j], Tv = acc[n + 8][j0 + j];
            mS = fmaxf(mS, Sv * inv_s[c]);
            mT = fmaxf(mT, Tv * inv_s[64 + c]);
            mM = fmaxf(mM, (Sv + Tv) * inv_s[128 + c]);
        }
        mS = qmax(mS); mT = qmax(mT); mM = qmax(mM);
        float zS = 0.f, zT = 0.f, zM = 0.f;
        #pragma unroll
        for (int i = 0; i < 16; ++i) {
            int n = i >> 1, j = i & 1, c = n * 8 + 2 * t + j;
            float Sv = acc[n][j0 + j], Tv = acc[n + 8][j0 + j];
            zS += __expf(Sv * inv_s[c] - mS);
            zT += __expf(Tv * inv_s[64 + c] - mT);
            zM += __expf((Sv + Tv) * inv_s[128 + c] - mM);
        }
        zS = qsum(zS); zT = qsum(zT); zM = qsum(zM);
        float lseS = mS + __logf(zS), lseT = mT + __logf(zT), lseM = mM + __logf(zM);
        float J = 0.f;
        #pragma unroll
        for (int i = 0; i < 16; ++i) {
            int n = i >> 1, j = i & 1, c = n * 8 + 2 * t + j;
            float Sv = acc[n][j0 + j], Tv = acc[n + 8][j0 + j];
            float ls = Sv * inv_s[c] - lseS;
            float lt = Tv * inv_s[64 + c] - lseT;
            float lm = (Sv + Tv) * inv_s[128 + c] - lseM;
            float es = __expf(ls), et = __expf(lt), em = __expf(lm);
            J += (et - es) * (lt - ls) + (em - es) * (lm - ls) + (em - et) * (lm - lt);
        }
        Jtot += qsum(J);
    }
    Jtot += __shfl_xor_sync(~0u, Jtot, 4);
    Jtot += __shfl_xor_sync(~0u, Jtot, 8);
    Jtot += __shfl_xor_sync(~0u, Jtot, 16);
    if (lane == 0) red[w] = Jtot;
    __syncthreads();
    if (tid == 0) {
        float bs = 0.f;
        #pragma unroll
        for (int i = 0; i < 8; ++i) bs += red[i];
        atomicAdd(&g_acc, (double)bs);
    }
}

__global__ void k_final(float* out) {
    out[0] = (float)(g_acc * (0.5 / (3.0 * 131072.0 * 64.0)));
}

extern "C" void kernel_launch(void* const* d_in, const int* in_sizes, int n_in,
                              void* d_out, int out_size) {
    const float* src = (const float*)d_in[0];
    const float* trg = (const float*)d_in[1];
    const int*   sl  = (const int*)d_in[2];
    const int*   tl  = (const int*)d_in[3];

    cudaFuncSetAttribute(k_segsum, cudaFuncAttributeMaxDynamicSharedMemorySize, 98304);
    cudaFuncSetAttribute(k_main,   cudaFuncAttributeMaxDynamicSharedMemorySize, SMEM_MAIN);

    k_detect<<<1, 1>>>(sl);
    k_zero<<<1, 256>>>();
    k_hist<<<64, 256>>>(sl, tl);
    k_segsum<<<512, 128, 98304>>>(src, trg, sl, tl);
    k_red<<<256, 512>>>();
    k_prep<<<64, 512>>>();
    k_main<<<1024, 256, SMEM_MAIN>>>();
    k_final<<<1, 1>>>((float*)d_out);
}

// round 9
// speedup vs baseline: 2.4052x; 1.0127x over previous
#include <cuda_runtime.h>
#include <cuda_bf16.h>
#include <cstdint>

#define NCLS 64
#define DIM 256
#define NROWS 65536
#define TOTROWS 131072

__device__ __align__(16) __nv_bfloat16 g_featbf[(size_t)TOTROWS * DIM];
__device__ float  g_scratch[2 * 256 * NCLS * 256];     // 32MB partial bins
__device__ float  g_wsum4[4 * 32768];
__device__ int    g_icnt[2][NCLS];
__device__ __align__(16) __nv_bfloat16 g_wbf[4 * 8192];  // W bf16 swizzled, cols interleaved
__device__ float  g_inv[3 * NCLS];
__device__ double g_acc;
__device__ int    g_lstride;

__device__ __forceinline__ uint32_t smem_u32(const void* p) {
    uint32_t r;
    asm("{ .reg .u64 t; cvta.to.shared.u64 t, %1; cvt.u32.u64 %0, t; }" : "=r"(r) : "l"(p));
    return r;
}
__device__ __forceinline__ void cpa16(uint32_t dst, const void* src) {
    asm volatile("cp.async.cg.shared.global [%0], [%1], 16;" :: "r"(dst), "l"(src));
}
__device__ __forceinline__ void cp_commit() { asm volatile("cp.async.commit_group;"); }
template<int N> __device__ __forceinline__ void cp_wait() {
    asm volatile("cp.async.wait_group %0;" :: "n"(N));
}
__device__ __forceinline__ uint32_t lds_u32(uint32_t a) {
    uint32_t v; asm volatile("ld.shared.b32 %0, [%1];" : "=r"(v) : "r"(a)); return v;
}
__device__ __forceinline__ void mma_bf16(float* d, const uint32_t* a, const uint32_t* b) {
    asm volatile("mma.sync.aligned.m16n8k16.row.col.f32.bf16.bf16.f32 "
        "{%0,%1,%2,%3}, {%4,%5,%6,%7}, {%8,%9}, {%0,%1,%2,%3};"
        : "+f"(d[0]), "+f"(d[1]), "+f"(d[2]), "+f"(d[3])
        : "r"(a[0]), "r"(a[1]), "r"(a[2]), "r"(a[3]), "r"(b[0]), "r"(b[1]));
}
__device__ __forceinline__ float qmax(float v) {
    v = fmaxf(v, __shfl_xor_sync(~0u, v, 1));
    v = fmaxf(v, __shfl_xor_sync(~0u, v, 2));
    return v;
}
__device__ __forceinline__ float qsum(float v) {
    v += __shfl_xor_sync(~0u, v, 1);
    v += __shfl_xor_sync(~0u, v, 2);
    return v;
}

__global__ void k_detect(const int* __restrict__ lbl) {
    bool oz = true;
    #pragma unroll
    for (int i = 0; i < 64; ++i) oz &= (lbl[2 * i + 1] == 0);
    g_lstride = oz ? 2 : 1;
}

__global__ void k_zero() {
    int i = threadIdx.x;
    if (i < 128) ((int*)g_icnt)[i] = 0;
    if (i == 128) g_acc = 0.0;
}

__global__ void __launch_bounds__(256) k_hist(const int* __restrict__ sl,
                                              const int* __restrict__ tl) {
    __shared__ int h[NCLS];
    const int feat = blockIdx.x >> 5;
    const int* lp = feat ? tl : sl;
    const int ls = g_lstride, tid = threadIdx.x;
    if (tid < NCLS) h[tid] = 0;
    __syncthreads();
    const int base = (blockIdx.x & 31) * 2048;
    #pragma unroll
    for (int i = 0; i < 8; ++i)
        atomicAdd(&h[lp[(base + tid + i * 256) * ls] & 63], 1);
    __syncthreads();
    if (tid < NCLS) atomicAdd(&g_icnt[feat][tid], h[tid]);
}

// ---- segment sums (R7 winner, unchanged): 4-stage cp.async ring ----
__global__ void __launch_bounds__(128) k_segsum(const float* __restrict__ src,
        const float* __restrict__ trg, const int* __restrict__ sl,
        const int* __restrict__ tl) {
    extern __shared__ float smf[];
    float2* bins = (float2*)(smf + 4 * 2048);
    __shared__ int lbl_s[256];
    const int feat = blockIdx.x >> 8, chunk = blockIdx.x & 255;
    const float* fp = feat ? trg : src;
    const int*   lp = feat ? tl : sl;
    const int ls = g_lstride, tid = threadIdx.x;
    const int base = chunk * 256;
    const uint32_t sbs = smem_u32(smf);
    const float* fin = fp + (size_t)base * DIM;

    #pragma unroll
    for (int s = 0; s < 3; ++s) {
        #pragma unroll
        for (int j = 0; j < 4; ++j) {
            int uu = j * 128 + tid;
            cpa16(sbs + (uint32_t)(s * 8192 + uu * 16), fin + (size_t)s * 2048 + uu * 4);
        }
        cp_commit();
    }

    lbl_s[tid]       = lp[(base + tid) * ls] & 63;
    lbl_s[tid + 128] = lp[(base + tid + 128) * ls] & 63;
    #pragma unroll
    for (int c = 0; c < NCLS; ++c) bins[c * 128 + tid] = make_float2(0.f, 0.f);

    __nv_bfloat162* outb = (__nv_bfloat162*)g_featbf
                         + (size_t)(feat * NROWS + base) * 128 + tid;

    for (int s = 0; s < 32; ++s) {
        if (s + 3 < 32) {
            #pragma unroll
            for (int j = 0; j < 4; ++j) {
                int uu = j * 128 + tid;
                cpa16(sbs + (uint32_t)((((s + 3) & 3) * 8192) + uu * 16),
                      fin + (size_t)(s + 3) * 2048 + uu * 4);
            }
        }
        cp_commit();
        cp_wait<3>();
        __syncthreads();

        const float2* sp = (const float2*)(smf + (s & 3) * 2048);
        #pragma unroll
        for (int i = 0; i < 8; ++i) {
            int r = s * 8 + i;
            float2 v = sp[i * 128 + tid];
            outb[(size_t)r * 128] = __floats2bfloat162_rn(v.x, v.y);
            int c = lbl_s[r];
            float2 b = bins[c * 128 + tid];
            b.x += v.x; b.y += v.y;
            bins[c * 128 + tid] = b;
        }
        __syncthreads();
    }

    float2* sc = (float2*)g_scratch + ((size_t)(feat * 256 + chunk) * NCLS) * 128 + tid;
    #pragma unroll 8
    for (int c = 0; c < NCLS; ++c) sc[c * 128] = bins[c * 128 + tid];
}

// ---- reduce stage 1 ----
__global__ void __launch_bounds__(512) k_red() {
    int q = blockIdx.x * 512 + threadIdx.x;
    int quarter = q >> 15, elem = q & 32767;
    int cls = elem >> 8, k = elem & 255;
    int feat = cls >> 6, c = cls & 63;
    const float* p = g_scratch
        + ((size_t)(feat * 256 + quarter * 64) * NCLS + c) * 256 + k;
    float s = 0.f;
    #pragma unroll 8
    for (int ch = 0; ch < 64; ++ch) s += p[(size_t)ch * (NCLS * 256)];
    g_wsum4[quarter * 32768 + elem] = s;
}

// ---- reduce stage 2: W image with interleaved cols: nc = 2*(cls&63) | (cls>>6) ----
__global__ void __launch_bounds__(512) k_prep() {
    int idx = blockIdx.x * 512 + threadIdx.x;  // 0..32767
    float s = g_wsum4[idx] + g_wsum4[32768 + idx]
            + g_wsum4[65536 + idx] + g_wsum4[98304 + idx];
    int cls = idx >> 8, k = idx & 255;
    int nc = ((cls & 63) << 1) | (cls >> 6);   // col interleave: even=S, odd=T
    int kc = k >> 6, u = (k >> 3) & 7, e = k & 7;
    int phys = nc * 8 + (u ^ (nc & 7));
    g_wbf[kc * 8192 + phys * 8 + e] = __float2bfloat16(s);
    if (idx < 3 * NCLS) {
        int which = idx >> 6, c2 = idx & 63;
        float cs = (float)g_icnt[0][c2], ct = (float)g_icnt[1][c2];
        g_inv[idx] = (which == 0) ? 1.f / cs : (which == 1) ? 1.f / ct : 1.f / (cs + ct);
    }
}

// ---- fused bf16 GEMM + softmax/KL: 1024 blocks x 256 thr, warps 2m x 4n ----
// warp tile m64 x n32; W streamed per K-chunk (L2-hot); cols interleaved (S,T) pairs
#define FB_OFF 0
#define WB_OFF 32768
#define PMZ_OFF 65536
#define LSE_OFF 77824
#define INV_OFF 79360
#define RED_OFF 80128
#define SMEM_MAIN 80160

__global__ void __launch_bounds__(256, 2) k_main() {
    extern __shared__ unsigned char sm[];
    float2* pmz  = (float2*)(sm + PMZ_OFF);    // [128 rows][4 wn][3 distro] (m,z)
    float*  lses = (float*)(sm + LSE_OFF);     // [128][3]
    float*  inv_s = (float*)(sm + INV_OFF);
    float*  red  = (float*)(sm + RED_OFF);
    const uint32_t sb = smem_u32(sm);
    const int tid = threadIdx.x, w = tid >> 5, lane = tid & 31;
    const int g = lane >> 2, t = lane & 3;
    const int wm = w >> 2, wn = w & 3;

    if (tid < 192) inv_s[tid] = g_inv[tid];

    const __nv_bfloat16* frow = g_featbf + (size_t)blockIdx.x * 128 * DIM;

    // stage chunk 0 (F swizzled + W identity)
    #pragma unroll
    for (int j = 0; j < 4; ++j) {
        int uu = j * 256 + tid, row = uu >> 3, u = uu & 7;
        cpa16(sb + FB_OFF + (uint32_t)(row * 8 + (u ^ (row & 7))) * 16,
              frow + (size_t)row * DIM + u * 8);
    }
    #pragma unroll
    for (int j = 0; j < 4; ++j) {
        int uu = j * 256 + tid;
        cpa16(sb + WB_OFF + uu * 16, g_wbf + uu * 8);
    }
    cp_commit();

    float acc[4][4][4];
    #pragma unroll
    for (int x = 0; x < 4; ++x)
        #pragma unroll
        for (int y = 0; y < 4; ++y)
            #pragma unroll
            for (int z = 0; z < 4; ++z) acc[x][y][z] = 0.f;

    #pragma unroll
    for (int kc = 0; kc < 4; ++kc) {
        if (kc < 3) {
            int nb = (kc + 1) & 1;
            #pragma unroll
            for (int j = 0; j < 4; ++j) {
                int uu = j * 256 + tid, row = uu >> 3, u = uu & 7;
                cpa16(sb + FB_OFF + nb * 16384 + (uint32_t)(row * 8 + (u ^ (row & 7))) * 16,
                      frow + (size_t)row * DIM + (kc + 1) * 64 + u * 8);
            }
            #pragma unroll
            for (int j = 0; j < 4; ++j) {
                int uu = j * 256 + tid;
                cpa16(sb + WB_OFF + nb * 16384 + uu * 16, g_wbf + (kc + 1) * 8192 + uu * 8);
            }
            cp_commit();
            cp_wait<1>();
        } else {
            cp_wait<0>();
        }
        __syncthreads();

        const uint32_t fb = sb + FB_OFF + (kc & 1) * 16384;
        const uint32_t wb = sb + WB_OFF + (kc & 1) * 16384;
        #pragma unroll
        for (int s = 0; s < 4; ++s) {
            uint32_t a[4][4], b[4][2];
            #pragma unroll
            for (int mt = 0; mt < 4; ++mt) {
                int r0 = wm * 64 + mt * 16 + g, r1 = r0 + 8;
                a[mt][0] = lds_u32(fb + (uint32_t)(r0 * 8 + ((2*s)   ^ (r0 & 7))) * 16 + 4 * t);
                a[mt][1] = lds_u32(fb + (uint32_t)(r1 * 8 + ((2*s)   ^ (r1 & 7))) * 16 + 4 * t);
                a[mt][2] = lds_u32(fb + (uint32_t)(r0 * 8 + ((2*s+1) ^ (r0 & 7))) * 16 + 4 * t);
                a[mt][3] = lds_u32(fb + (uint32_t)(r1 * 8 + ((2*s+1) ^ (r1 & 7))) * 16 + 4 * t);
            }
            #pragma unroll
            for (int nt = 0; nt < 4; ++nt) {
                int cn = wn * 32 + nt * 8 + g;
                b[nt][0] = lds_u32(wb + (uint32_t)(cn * 8 + ((2*s)   ^ (cn & 7))) * 16 + 4 * t);
                b[nt][1] = lds_u32(wb + (uint32_t)(cn * 8 + ((2*s+1) ^ (cn & 7))) * 16 + 4 * t);
            }
            #pragma unroll
            for (int mt = 0; mt < 4; ++mt)
                #pragma unroll
                for (int nt = 0; nt < 4; ++nt)
                    mma_bf16(acc[mt][nt], a[mt], b[nt]);
        }
        __syncthreads();
    }

    // ---- epilogue phase 1: per-warp partial (m, z) over its 16 classes ----
    float invS[4], invT[4], invM[4];
    #pragma unroll
    for (int nt = 0; nt < 4; ++nt) {
        int c = wn * 16 + nt * 4 + t;
        invS[nt] = inv_s[c]; invT[nt] = inv_s[64 + c]; invM[nt] = inv_s[128 + c];
    }
    #pragma unroll
    for (int mt = 0; mt < 4; ++mt) {
        #pragma unroll
        for (int h = 0; h < 2; ++h) {
            int row = wm * 64 + mt * 16 + g + 8 * h;
            float mS = -1e30f, mT = -1e30f, mM = -1e30f;
            #pragma unroll
            for (int nt = 0; nt < 4; ++nt) {
                float Sr = acc[mt][nt][2*h], Tr = acc[mt][nt][2*h+1];
                mS = fmaxf(mS, Sr * invS[nt]);
                mT = fmaxf(mT, Tr * invT[nt]);
                mM = fmaxf(mM, (Sr + Tr) * invM[nt]);
            }
            mS = qmax(mS); mT = qmax(mT); mM = qmax(mM);
            float zS = 0.f, zT = 0.f, zM = 0.f;
            #pragma unroll
            for (int nt = 0; nt < 4; ++nt) {
                float Sr = acc[mt][nt][2*h], Tr = acc[mt][nt][2*h+1];
                zS += __expf(Sr * invS[nt] - mS);
                zT += __expf(Tr * invT[nt] - mT);
                zM += __expf((Sr + Tr) * invM[nt] - mM);
            }
            zS = qsum(zS); zT = qsum(zT); zM = qsum(zM);
            if (t == 0) {
                pmz[(row * 4 + wn) * 3 + 0] = make_float2(mS, zS);
                pmz[(row * 4 + wn) * 3 + 1] = make_float2(mT, zT);
                pmz[(row * 4 + wn) * 3 + 2] = make_float2(mM, zM);
            }
        }
    }
    __syncthreads();

    // ---- phase 2: per-row lse combine (128 threads, one row each) ----
    if (tid < 128) {
        #pragma unroll
        for (int d = 0; d < 3; ++d) {
            float2 p0 = pmz[(tid * 4 + 0) * 3 + d], p1 = pmz[(tid * 4 + 1) * 3 + d];
            float2 p2 = pmz[(tid * 4 + 2) * 3 + d], p3 = pmz[(tid * 4 + 3) * 3 + d];
            float m = fmaxf(fmaxf(p0.x, p1.x), fmaxf(p2.x, p3.x));
            float z = p0.y * __expf(p0.x - m) + p1.y * __expf(p1.x - m)
                    + p2.y * __expf(p2.x - m) + p3.y * __expf(p3.x - m);
            lses[tid * 3 + d] = m + __logf(z);
        }
    }
    __syncthreads();

    // ---- phase 3: KL terms ----
    float J = 0.f;
    #pragma unroll
    for (int mt = 0; mt < 4; ++mt) {
        #pragma unroll
        for (int h = 0; h < 2; ++h) {
            int row = wm * 64 + mt * 16 + g + 8 * h;
            float lseS = lses[row * 3 + 0], lseT = lses[row * 3 + 1], lseM = lses[row * 3 + 2];
            #pragma unroll
            for (int nt = 0; nt < 4; ++nt) {
                float Sr = acc[mt][nt][2*h], Tr = acc[mt][nt][2*h+1];
                float ls = Sr * invS[nt] - lseS;
                float lt = Tr * invT[nt] - lseT;
                float lm = (Sr + Tr) * invM[nt] - lseM;
                float es = __expf(ls), et = __expf(lt), em = __expf(lm);
                J += (et - es) * (lt - ls) + (em - es) * (lm - ls) + (em - et) * (lm - lt);
            }
        }
    }
    #pragma unroll
    for (int o = 16; o; o >>= 1) J += __shfl_xor_sync(~0u, J, o);
    if (lane == 0) red[w] = J;
    __syncthreads();
    if (tid == 0) {
        float bs = 0.f;
        #pragma unroll
        for (int i = 0; i < 8; ++i) bs += red[i];
        atomicAdd(&g_acc, (double)bs);
    }
}

__global__ void k_final(float* out) {
    out[0] = (float)(g_acc * (0.5 / (3.0 * 131072.0 * 64.0)));
}

extern "C" void kernel_launch(void* const* d_in, const int* in_sizes, int n_in,
                              void* d_out, int out_size) {
    const float* src = (const float*)d_in[0];
    const float* trg = (const float*)d_in[1];
    const int*   sl  = (const int*)d_in[2];
    const int*   tl  = (const int*)d_in[3];

    cudaFuncSetAttribute(k_segsum, cudaFuncAttributeMaxDynamicSharedMemorySize, 98304);
    cudaFuncSetAttribute(k_main,   cudaFuncAttributeMaxDynamicSharedMemorySize, SMEM_MAIN);

    k_detect<<<1, 1>>>(sl);
    k_zero<<<1, 256>>>();
    k_hist<<<64, 256>>>(sl, tl);
    k_segsum<<<512, 128, 98304>>>(src, trg, sl, tl);
    k_red<<<256, 512>>>();
    k_prep<<<64, 512>>>();
    k_main<<<1024, 256, SMEM_MAIN>>>();
    k_final<<<1, 1>>>((float*)d_out);
}

// round 10
// speedup vs baseline: 2.5039x; 1.0410x over previous
#include <cuda_runtime.h>
#include <cuda_bf16.h>
#include <cstdint>

#define NCLS 64
#define DIM 256
#define NROWS 65536
#define TOTROWS 131072

__device__ __align__(16) __nv_bfloat16 g_featbf[(size_t)TOTROWS * DIM];
__device__ __align__(16) __nv_bfloat162 g_scratch_bf[2 * 256 * NCLS * 128]; // 16MB
__device__ float  g_wsum4[4 * 32768];
__device__ int    g_icnt[2][NCLS];
__device__ __align__(16) __nv_bfloat16 g_wbf[4 * 8192];  // W bf16 swizzled, cols interleaved
__device__ float  g_inv[3 * NCLS];
__device__ double g_acc;
__device__ int    g_lstride;

__device__ __forceinline__ uint32_t smem_u32(const void* p) {
    uint32_t r;
    asm("{ .reg .u64 t; cvta.to.shared.u64 t, %1; cvt.u32.u64 %0, t; }" : "=r"(r) : "l"(p));
    return r;
}
__device__ __forceinline__ void cpa16(uint32_t dst, const void* src) {
    asm volatile("cp.async.cg.shared.global [%0], [%1], 16;" :: "r"(dst), "l"(src));
}
__device__ __forceinline__ void cp_commit() { asm volatile("cp.async.commit_group;"); }
template<int N> __device__ __forceinline__ void cp_wait() {
    asm volatile("cp.async.wait_group %0;" :: "n"(N));
}
__device__ __forceinline__ uint32_t lds_u32(uint32_t a) {
    uint32_t v; asm volatile("ld.shared.b32 %0, [%1];" : "=r"(v) : "r"(a)); return v;
}
__device__ __forceinline__ void mma_bf16(float* d, const uint32_t* a, const uint32_t* b) {
    asm volatile("mma.sync.aligned.m16n8k16.row.col.f32.bf16.bf16.f32 "
        "{%0,%1,%2,%3}, {%4,%5,%6,%7}, {%8,%9}, {%0,%1,%2,%3};"
        : "+f"(d[0]), "+f"(d[1]), "+f"(d[2]), "+f"(d[3])
        : "r"(a[0]), "r"(a[1]), "r"(a[2]), "r"(a[3]), "r"(b[0]), "r"(b[1]));
}
__device__ __forceinline__ float qsum(float v) {
    v += __shfl_xor_sync(~0u, v, 1);
    v += __shfl_xor_sync(~0u, v, 2);
    return v;
}

__global__ void k_detect(const int* __restrict__ lbl) {
    bool oz = true;
    #pragma unroll
    for (int i = 0; i < 64; ++i) oz &= (lbl[2 * i + 1] == 0);
    g_lstride = oz ? 2 : 1;
}

__global__ void k_zero() {
    int i = threadIdx.x;
    if (i < 128) ((int*)g_icnt)[i] = 0;
    if (i == 128) g_acc = 0.0;
}

// ---- segment sums + label counts: 512 blocks x 128 thr, cp.async ring ----
__global__ void __launch_bounds__(128) k_segsum(const float* __restrict__ src,
        const float* __restrict__ trg, const int* __restrict__ sl,
        const int* __restrict__ tl) {
    extern __shared__ float smf[];             // [4][2048] ring + [64][128] float2 bins
    float2* bins = (float2*)(smf + 4 * 2048);
    __shared__ int lbl_s[256];
    const int feat = blockIdx.x >> 8, chunk = blockIdx.x & 255;
    const float* fp = feat ? trg : src;
    const int*   lp = feat ? tl : sl;
    const int ls = g_lstride, tid = threadIdx.x;
    const int base = chunk * 256;
    const uint32_t sbs = smem_u32(smf);
    const float* fin = fp + (size_t)base * DIM;

    #pragma unroll
    for (int s = 0; s < 3; ++s) {
        #pragma unroll
        for (int j = 0; j < 4; ++j) {
            int uu = j * 128 + tid;
            cpa16(sbs + (uint32_t)(s * 8192 + uu * 16), fin + (size_t)s * 2048 + uu * 4);
        }
        cp_commit();
    }

    lbl_s[tid]       = lp[(base + tid) * ls] & 63;
    lbl_s[tid + 128] = lp[(base + tid + 128) * ls] & 63;
    #pragma unroll
    for (int c = 0; c < NCLS; ++c) bins[c * 128 + tid] = make_float2(0.f, 0.f);

    __nv_bfloat162* outb = (__nv_bfloat162*)g_featbf
                         + (size_t)(feat * NROWS + base) * 128 + tid;

    for (int s = 0; s < 32; ++s) {
        if (s + 3 < 32) {
            #pragma unroll
            for (int j = 0; j < 4; ++j) {
                int uu = j * 128 + tid;
                cpa16(sbs + (uint32_t)((((s + 3) & 3) * 8192) + uu * 16),
                      fin + (size_t)(s + 3) * 2048 + uu * 4);
            }
        }
        cp_commit();
        cp_wait<3>();
        __syncthreads();

        const float2* sp = (const float2*)(smf + (s & 3) * 2048);
        #pragma unroll
        for (int i = 0; i < 8; ++i) {
            int r = s * 8 + i;
            float2 v = sp[i * 128 + tid];
            outb[(size_t)r * 128] = __floats2bfloat162_rn(v.x, v.y);
            int c = lbl_s[r];
            float2 b = bins[c * 128 + tid];
            b.x += v.x; b.y += v.y;
            bins[c * 128 + tid] = b;
        }
        __syncthreads();
    }

    // fused label histogram (labels already in smem)
    if (tid < NCLS) {
        int cnt = 0;
        #pragma unroll 8
        for (int r = 0; r < 256; ++r) cnt += (lbl_s[r] == tid);
        atomicAdd(&g_icnt[feat][tid], cnt);
    }

    __nv_bfloat162* sc = g_scratch_bf + ((size_t)(feat * 256 + chunk) * NCLS) * 128 + tid;
    #pragma unroll 8
    for (int c = 0; c < NCLS; ++c)
        sc[c * 128] = __float22bfloat162_rn(bins[c * 128 + tid]);
}

// ---- reduce stage 1: bf16 scratch -> quarter sums (float) ----
__global__ void __launch_bounds__(256) k_red() {
    int q = blockIdx.x * 256 + threadIdx.x;    // 0..65535
    int quarter = q >> 14, e2 = q & 16383;
    int cls = e2 >> 7, k2 = e2 & 127;
    int feat = cls >> 6, c = cls & 63;
    const __nv_bfloat162* p = g_scratch_bf
        + ((size_t)(feat * 256 + quarter * 64) * NCLS + c) * 128 + k2;
    float2 s = make_float2(0.f, 0.f);
    #pragma unroll 8
    for (int ch = 0; ch < 64; ++ch) {
        float2 v = __bfloat1622float2(p[(size_t)ch * (NCLS * 128)]);
        s.x += v.x; s.y += v.y;
    }
    ((float2*)g_wsum4)[quarter * 16384 + cls * 128 + k2] = s;
}

// ---- reduce stage 2: W image, interleaved cols: nc = 2*(cls&63) | (cls>>6) ----
__global__ void __launch_bounds__(512) k_prep() {
    int idx = blockIdx.x * 512 + threadIdx.x;  // 0..32767
    float s = g_wsum4[idx] + g_wsum4[32768 + idx]
            + g_wsum4[65536 + idx] + g_wsum4[98304 + idx];
    int cls = idx >> 8, k = idx & 255;
    int nc = ((cls & 63) << 1) | (cls >> 6);
    int kc = k >> 6, u = (k >> 3) & 7, e = k & 7;
    int phys = nc * 8 + (u ^ (nc & 7));
    g_wbf[kc * 8192 + phys * 8 + e] = __float2bfloat16(s);
    if (idx < 3 * NCLS) {
        int which = idx >> 6, c2 = idx & 63;
        float cs = (float)g_icnt[0][c2], ct = (float)g_icnt[1][c2];
        g_inv[idx] = (which == 0) ? 1.f / cs : (which == 1) ? 1.f / ct : 1.f / (cs + ct);
    }
}

// ---- fused bf16 GEMM + moment-based KL: 1024 blocks x 256 thr, warps 2m x 4n ----
// W fully resident (64KB); F double-buffered; epilogue = single-pass moments
#define WB_OFF 0
#define FB_OFF 65536
#define PM_OFF 65536            /* overlays F after mainloop: [128][4][12] = 24KB */
#define INV_OFF 98304
#define RED_OFF 99072
#define SMEM_MAIN 99104

__global__ void __launch_bounds__(256, 2) k_main() {
    extern __shared__ unsigned char sm[];
    float* inv_s = (float*)(sm + INV_OFF);
    float* red   = (float*)(sm + RED_OFF);
    const uint32_t sb = smem_u32(sm);
    const int tid = threadIdx.x, w = tid >> 5, lane = tid & 31;
    const int g = lane >> 2, t = lane & 3;
    const int wm = w >> 2, wn = w & 3;

    if (tid < 192) inv_s[tid] = g_inv[tid];

    // stage full W (64KB = 4096 units), group 0
    #pragma unroll
    for (int j = 0; j < 16; ++j) {
        int uu = j * 256 + tid;
        cpa16(sb + WB_OFF + uu * 16, g_wbf + uu * 8);
    }
    cp_commit();

    const __nv_bfloat16* frow = g_featbf + (size_t)blockIdx.x * 128 * DIM;
    // stage F chunk 0, group 1
    #pragma unroll
    for (int j = 0; j < 4; ++j) {
        int uu = j * 256 + tid, row = uu >> 3, u = uu & 7;
        cpa16(sb + FB_OFF + (uint32_t)(row * 8 + (u ^ (row & 7))) * 16,
              frow + (size_t)row * DIM + u * 8);
    }
    cp_commit();

    float acc[4][4][4];
    #pragma unroll
    for (int x = 0; x < 4; ++x)
        #pragma unroll
        for (int y = 0; y < 4; ++y)
            #pragma unroll
            for (int z = 0; z < 4; ++z) acc[x][y][z] = 0.f;

    #pragma unroll
    for (int kc = 0; kc < 4; ++kc) {
        if (kc < 3) {
            int nb = (kc + 1) & 1;
            #pragma unroll
            for (int j = 0; j < 4; ++j) {
                int uu = j * 256 + tid, row = uu >> 3, u = uu & 7;
                cpa16(sb + FB_OFF + nb * 16384 + (uint32_t)(row * 8 + (u ^ (row & 7))) * 16,
                      frow + (size_t)row * DIM + (kc + 1) * 64 + u * 8);
            }
            cp_commit();
            cp_wait<1>();
        } else {
            cp_wait<0>();
        }
        __syncthreads();

        const uint32_t fb = sb + FB_OFF + (kc & 1) * 16384;
        const uint32_t wb = sb + WB_OFF + kc * 16384;
        #pragma unroll
        for (int s = 0; s < 4; ++s) {
            uint32_t a[4][4], b[4][2];
            #pragma unroll
            for (int mt = 0; mt < 4; ++mt) {
                int r0 = wm * 64 + mt * 16 + g, r1 = r0 + 8;
                a[mt][0] = lds_u32(fb + (uint32_t)(r0 * 8 + ((2*s)   ^ (r0 & 7))) * 16 + 4 * t);
                a[mt][1] = lds_u32(fb + (uint32_t)(r1 * 8 + ((2*s)   ^ (r1 & 7))) * 16 + 4 * t);
                a[mt][2] = lds_u32(fb + (uint32_t)(r0 * 8 + ((2*s+1) ^ (r0 & 7))) * 16 + 4 * t);
                a[mt][3] = lds_u32(fb + (uint32_t)(r1 * 8 + ((2*s+1) ^ (r1 & 7))) * 16 + 4 * t);
            }
            #pragma unroll
            for (int nt = 0; nt < 4; ++nt) {
                int cn = wn * 32 + nt * 8 + g;
                b[nt][0] = lds_u32(wb + (uint32_t)(cn * 8 + ((2*s)   ^ (cn & 7))) * 16 + 4 * t);
                b[nt][1] = lds_u32(wb + (uint32_t)(cn * 8 + ((2*s+1) ^ (cn & 7))) * 16 + 4 * t);
            }
            #pragma unroll
            for (int mt = 0; mt < 4; ++mt)
                #pragma unroll
                for (int nt = 0; nt < 4; ++nt)
                    mma_bf16(acc[mt][nt], a[mt], b[nt]);
        }
        __syncthreads();
    }

    // ---- epilogue: single-pass moments; J needs no lse (sum(q-p)=0 identity) ----
    float invS[4], invT[4], invM[4];
    #pragma unroll
    for (int nt = 0; nt < 4; ++nt) {
        int c = wn * 16 + nt * 4 + t;
        invS[nt] = inv_s[c]; invT[nt] = inv_s[64 + c]; invM[nt] = inv_s[128 + c];
    }
    float* pm = (float*)(sm + PM_OFF);
    #pragma unroll
    for (int mt = 0; mt < 4; ++mt) {
        #pragma unroll
        for (int h = 0; h < 2; ++h) {
            float Z0 = 0.f, Z1 = 0.f, Z2 = 0.f;
            float A[9] = {0.f, 0.f, 0.f, 0.f, 0.f, 0.f, 0.f, 0.f, 0.f};
            #pragma unroll
            for (int nt = 0; nt < 4; ++nt) {
                float Sr = acc[mt][nt][2*h], Tr = acc[mt][nt][2*h+1];
                float ps = Sr * invS[nt], pt = Tr * invT[nt], pv = (Sr + Tr) * invM[nt];
                float eS = __expf(ps), eT = __expf(pt), eM = __expf(pv);
                Z0 += eS; Z1 += eT; Z2 += eM;
                A[0] += eS * ps; A[1] += eS * pt; A[2] += eS * pv;
                A[3] += eT * ps; A[4] += eT * pt; A[5] += eT * pv;
                A[6] += eM * ps; A[7] += eM * pt; A[8] += eM * pv;
            }
            Z0 = qsum(Z0); Z1 = qsum(Z1); Z2 = qsum(Z2);
            #pragma unroll
            for (int i = 0; i < 9; ++i) A[i] = qsum(A[i]);
            if (t == 0) {
                int row = wm * 64 + mt * 16 + g + 8 * h;
                float* d = pm + (row * 4 + wn) * 12;
                d[0] = Z0; d[1] = Z1; d[2] = Z2;
                #pragma unroll
                for (int i = 0; i < 9; ++i) d[3 + i] = A[i];
            }
        }
    }
    __syncthreads();

    float Jr = 0.f;
    if (tid < 128) {
        float v[12];
        #pragma unroll
        for (int i = 0; i < 12; ++i)
            v[i] = pm[(tid * 4 + 0) * 12 + i] + pm[(tid * 4 + 1) * 12 + i]
                 + pm[(tid * 4 + 2) * 12 + i] + pm[(tid * 4 + 3) * 12 + i];
        Jr = __fdividef(2.f * v[3] - v[4] - v[5], v[0])
           + __fdividef(2.f * v[7] - v[6] - v[8], v[1])
           + __fdividef(2.f * v[11] - v[9] - v[10], v[2]);
    }
    #pragma unroll
    for (int o = 16; o; o >>= 1) Jr += __shfl_xor_sync(~0u, Jr, o);
    if (lane == 0) red[w] = Jr;
    __syncthreads();
    if (tid == 0) {
        float bs = 0.f;
        #pragma unroll
        for (int i = 0; i < 8; ++i) bs += red[i];
        atomicAdd(&g_acc, (double)bs);
    }
}

__global__ void k_final(float* out) {
    out[0] = (float)(g_acc * (0.5 / (3.0 * 131072.0 * 64.0)));
}

extern "C" void kernel_launch(void* const* d_in, const int* in_sizes, int n_in,
                              void* d_out, int out_size) {
    const float* src = (const float*)d_in[0];
    const float* trg = (const float*)d_in[1];
    const int*   sl  = (const int*)d_in[2];
    const int*   tl  = (const int*)d_in[3];

    cudaFuncSetAttribute(k_segsum, cudaFuncAttributeMaxDynamicSharedMemorySize, 98304);
    cudaFuncSetAttribute(k_main,   cudaFuncAttributeMaxDynamicSharedMemorySize, SMEM_MAIN);

    k_detect<<<1, 1>>>(sl);
    k_zero<<<1, 256>>>();
    k_segsum<<<512, 128, 98304>>>(src, trg, sl, tl);
    k_red<<<256, 256>>>();
    k_prep<<<64, 512>>>();
    k_main<<<1024, 256, SMEM_MAIN>>>();
    k_final<<<1, 1>>>((float*)d_out);
}

// round 11
// speedup vs baseline: 2.6694x; 1.0661x over previous
#include <cuda_runtime.h>
#include <cuda_bf16.h>
#include <cstdint>

#define NCLS 64
#define DIM 256
#define NROWS 65536
#define TOTROWS 131072

__device__ __align__(16) __nv_bfloat16 g_featbf[(size_t)TOTROWS * DIM];
__device__ __align__(16) __nv_bfloat162 g_scratch_bf[2 * 256 * NCLS * 128]; // 16MB
__device__ __align__(16) float g_wpart[4096 * 16 * 8];   // 2MB partials, elem-major
__device__ int    g_icnt[2][NCLS];
__device__ __align__(16) __nv_bfloat16 g_wbf[4 * 8192];  // W bf16 swizzled, cols interleaved
__device__ float  g_inv[3 * NCLS];
__device__ double g_acc;
__device__ int    g_lstride;

__device__ __forceinline__ uint32_t smem_u32(const void* p) {
    uint32_t r;
    asm("{ .reg .u64 t; cvta.to.shared.u64 t, %1; cvt.u32.u64 %0, t; }" : "=r"(r) : "l"(p));
    return r;
}
__device__ __forceinline__ void cpa16(uint32_t dst, const void* src) {
    asm volatile("cp.async.cg.shared.global [%0], [%1], 16;" :: "r"(dst), "l"(src));
}
__device__ __forceinline__ void cp_commit() { asm volatile("cp.async.commit_group;"); }
template<int N> __device__ __forceinline__ void cp_wait() {
    asm volatile("cp.async.wait_group %0;" :: "n"(N));
}
__device__ __forceinline__ uint32_t lds_u32(uint32_t a) {
    uint32_t v; asm volatile("ld.shared.b32 %0, [%1];" : "=r"(v) : "r"(a)); return v;
}
__device__ __forceinline__ void mma_bf16(float* d, const uint32_t* a, const uint32_t* b) {
    asm volatile("mma.sync.aligned.m16n8k16.row.col.f32.bf16.bf16.f32 "
        "{%0,%1,%2,%3}, {%4,%5,%6,%7}, {%8,%9}, {%0,%1,%2,%3};"
        : "+f"(d[0]), "+f"(d[1]), "+f"(d[2]), "+f"(d[3])
        : "r"(a[0]), "r"(a[1]), "r"(a[2]), "r"(a[3]), "r"(b[0]), "r"(b[1]));
}
__device__ __forceinline__ float qsum(float v) {
    v += __shfl_xor_sync(~0u, v, 1);
    v += __shfl_xor_sync(~0u, v, 2);
    return v;
}

// ---- zero + label-dtype detect (merged) ----
__global__ void k_zero(const int* __restrict__ lbl) {
    int i = threadIdx.x;
    if (i < 128) ((int*)g_icnt)[i] = 0;
    if (i == 128) g_acc = 0.0;
    if (i == 129) {
        bool oz = true;
        #pragma unroll
        for (int j = 0; j < 64; ++j) oz &= (lbl[2 * j + 1] == 0);
        g_lstride = oz ? 2 : 1;
    }
}

// ---- segment sums + label counts: 512 blocks x 128 thr, 5-slot cp.async ring ----
__global__ void __launch_bounds__(128) k_segsum(const float* __restrict__ src,
        const float* __restrict__ trg, const int* __restrict__ sl,
        const int* __restrict__ tl) {
    extern __shared__ float smf[];             // [5][2048] ring + [64][128] float2 bins
    float2* bins = (float2*)(smf + 5 * 2048);
    __shared__ int lbl_s[256];
    const int feat = blockIdx.x >> 8, chunk = blockIdx.x & 255;
    const float* fp = feat ? trg : src;
    const int*   lp = feat ? tl : sl;
    const int ls = g_lstride, tid = threadIdx.x;
    const int base = chunk * 256;
    const uint32_t sbs = smem_u32(smf);
    const float* fin = fp + (size_t)base * DIM;

    #pragma unroll
    for (int s = 0; s < 4; ++s) {              // prologue: stages 0..3 -> slots 0..3
        #pragma unroll
        for (int j = 0; j < 4; ++j) {
            int uu = j * 128 + tid;
            cpa16(sbs + (uint32_t)(s * 8192 + uu * 16), fin + (size_t)s * 2048 + uu * 4);
        }
        cp_commit();
    }

    lbl_s[tid]       = lp[(base + tid) * ls] & 63;
    lbl_s[tid + 128] = lp[(base + tid + 128) * ls] & 63;
    #pragma unroll
    for (int c = 0; c < NCLS; ++c) bins[c * 128 + tid] = make_float2(0.f, 0.f);

    __nv_bfloat162* outb = (__nv_bfloat162*)g_featbf
                         + (size_t)(feat * NROWS + base) * 128 + tid;

    int ws = 4, ps = 0;
    for (int s = 0; s < 32; ++s) {
        if (s + 4 < 32) {
            #pragma unroll
            for (int j = 0; j < 4; ++j) {
                int uu = j * 128 + tid;
                cpa16(sbs + (uint32_t)(ws * 8192 + uu * 16),
                      fin + (size_t)(s + 4) * 2048 + uu * 4);
            }
        }
        cp_commit();       // possibly empty; keeps wait arithmetic exact
        cp_wait<4>();
        __syncthreads();

        const float2* sp = (const float2*)(smf + ps * 2048);
        #pragma unroll
        for (int i = 0; i < 8; ++i) {
            int r = s * 8 + i;
            float2 v = sp[i * 128 + tid];
            outb[(size_t)r * 128] = __floats2bfloat162_rn(v.x, v.y);
            int c = lbl_s[r];
            float2 b = bins[c * 128 + tid];
            b.x += v.x; b.y += v.y;
            bins[c * 128 + tid] = b;
        }
        __syncthreads();
        if (++ws == 5) ws = 0;
        if (++ps == 5) ps = 0;
    }

    if (tid < NCLS) {      // fused label histogram
        int cnt = 0;
        #pragma unroll 8
        for (int r = 0; r < 256; ++r) cnt += (lbl_s[r] == tid);
        atomicAdd(&g_icnt[feat][tid], cnt);
    }

    __nv_bfloat162* sc = g_scratch_bf + ((size_t)(feat * 256 + chunk) * NCLS) * 128 + tid;
    #pragma unroll 8
    for (int c = 0; c < NCLS; ++c)
        sc[c * 128] = __float22bfloat162_rn(bins[c * 128 + tid]);
}

// ---- reduce stage 1: 16 partials, uint4 loads, elem-major output ----
__global__ void __launch_bounds__(256) k_red() {
    int q = blockIdx.x * 256 + threadIdx.x;    // 0..65535
    int p = q >> 12;                            // partial 0..15
    int rem = q & 4095;                         // ef = cls*32 + quad
    int cls = rem >> 5, quad = rem & 31;
    int feat = cls >> 6, c = cls & 63;
    const uint4* srcp = (const uint4*)(g_scratch_bf
        + ((size_t)((feat * 256 + p * 16) * NCLS + c)) * 128 + quad * 4);
    float s[8] = {0.f, 0.f, 0.f, 0.f, 0.f, 0.f, 0.f, 0.f};
    #pragma unroll 16
    for (int ch = 0; ch < 16; ++ch) {
        uint4 v = srcp[(size_t)ch * 2048];      // chunk stride = 8192 bf162 = 2048 uint4
        const __nv_bfloat162* pv = (const __nv_bfloat162*)&v;
        #pragma unroll
        for (int t2 = 0; t2 < 4; ++t2) {
            float2 f = __bfloat1622float2(pv[t2]);
            s[2 * t2] += f.x; s[2 * t2 + 1] += f.y;
        }
    }
    float4* d = (float4*)(g_wpart + (size_t)rem * 128 + p * 8);
    d[0] = make_float4(s[0], s[1], s[2], s[3]);
    d[1] = make_float4(s[4], s[5], s[6], s[7]);
}

// ---- reduce stage 2: combine 16 partials, W image (interleaved cols), inv ----
__global__ void __launch_bounds__(512) k_prep() {
    int idx = blockIdx.x * 512 + threadIdx.x;  // 0..32767
    int ef = idx >> 3, j = idx & 7;
    float s = 0.f;
    #pragma unroll 16
    for (int p = 0; p < 16; ++p) s += g_wpart[(size_t)ef * 128 + p * 8 + j];
    int cls = ef >> 5, k = (ef & 31) * 8 + j;
    int nc = ((cls & 63) << 1) | (cls >> 6);
    int kc = k >> 6, u = (k >> 3) & 7, e = k & 7;
    g_wbf[kc * 8192 + (nc * 8 + (u ^ (nc & 7))) * 8 + e] = __float2bfloat16(s);
    if (idx < 3 * NCLS) {
        int which = idx >> 6, c2 = idx & 63;
        float cs = (float)g_icnt[0][c2], ct = (float)g_icnt[1][c2];
        g_inv[idx] = (which == 0) ? 1.f / cs : (which == 1) ? 1.f / ct : 1.f / (cs + ct);
    }
}

// ---- fused bf16 GEMM + moment-based KL (R10 winner, unchanged) ----
#define WB_OFF 0
#define FB_OFF 65536
#define PM_OFF 65536
#define INV_OFF 98304
#define RED_OFF 99072
#define SMEM_MAIN 99104

__global__ void __launch_bounds__(256, 2) k_main() {
    extern __shared__ unsigned char sm[];
    float* inv_s = (float*)(sm + INV_OFF);
    float* red   = (float*)(sm + RED_OFF);
    const uint32_t sb = smem_u32(sm);
    const int tid = threadIdx.x, w = tid >> 5, lane = tid & 31;
    const int g = lane >> 2, t = lane & 3;
    const int wm = w >> 2, wn = w & 3;

    if (tid < 192) inv_s[tid] = g_inv[tid];

    #pragma unroll
    for (int j = 0; j < 16; ++j) {
        int uu = j * 256 + tid;
        cpa16(sb + WB_OFF + uu * 16, g_wbf + uu * 8);
    }
    cp_commit();

    const __nv_bfloat16* frow = g_featbf + (size_t)blockIdx.x * 128 * DIM;
    #pragma unroll
    for (int j = 0; j < 4; ++j) {
        int uu = j * 256 + tid, row = uu >> 3, u = uu & 7;
        cpa16(sb + FB_OFF + (uint32_t)(row * 8 + (u ^ (row & 7))) * 16,
              frow + (size_t)row * DIM + u * 8);
    }
    cp_commit();

    float acc[4][4][4];
    #pragma unroll
    for (int x = 0; x < 4; ++x)
        #pragma unroll
        for (int y = 0; y < 4; ++y)
            #pragma unroll
            for (int z = 0; z < 4; ++z) acc[x][y][z] = 0.f;

    #pragma unroll
    for (int kc = 0; kc < 4; ++kc) {
        if (kc < 3) {
            int nb = (kc + 1) & 1;
            #pragma unroll
            for (int j = 0; j < 4; ++j) {
                int uu = j * 256 + tid, row = uu >> 3, u = uu & 7;
                cpa16(sb + FB_OFF + nb * 16384 + (uint32_t)(row * 8 + (u ^ (row & 7))) * 16,
                      frow + (size_t)row * DIM + (kc + 1) * 64 + u * 8);
            }
            cp_commit();
            cp_wait<1>();
        } else {
            cp_wait<0>();
        }
        __syncthreads();

        const uint32_t fb = sb + FB_OFF + (kc & 1) * 16384;
        const uint32_t wb = sb + WB_OFF + kc * 16384;
        #pragma unroll
        for (int s = 0; s < 4; ++s) {
            uint32_t a[4][4], b[4][2];
            #pragma unroll
            for (int mt = 0; mt < 4; ++mt) {
                int r0 = wm * 64 + mt * 16 + g, r1 = r0 + 8;
                a[mt][0] = lds_u32(fb + (uint32_t)(r0 * 8 + ((2*s)   ^ (r0 & 7))) * 16 + 4 * t);
                a[mt][1] = lds_u32(fb + (uint32_t)(r1 * 8 + ((2*s)   ^ (r1 & 7))) * 16 + 4 * t);
                a[mt][2] = lds_u32(fb + (uint32_t)(r0 * 8 + ((2*s+1) ^ (r0 & 7))) * 16 + 4 * t);
                a[mt][3] = lds_u32(fb + (uint32_t)(r1 * 8 + ((2*s+1) ^ (r1 & 7))) * 16 + 4 * t);
            }
            #pragma unroll
            for (int nt = 0; nt < 4; ++nt) {
                int cn = wn * 32 + nt * 8 + g;
                b[nt][0] = lds_u32(wb + (uint32_t)(cn * 8 + ((2*s)   ^ (cn & 7))) * 16 + 4 * t);
                b[nt][1] = lds_u32(wb + (uint32_t)(cn * 8 + ((2*s+1) ^ (cn & 7))) * 16 + 4 * t);
            }
            #pragma unroll
            for (int mt = 0; mt < 4; ++mt)
                #pragma unroll
                for (int nt = 0; nt < 4; ++nt)
                    mma_bf16(acc[mt][nt], a[mt], b[nt]);
        }
        __syncthreads();
    }

    float invS[4], invT[4], invM[4];
    #pragma unroll
    for (int nt = 0; nt < 4; ++nt) {
        int c = wn * 16 + nt * 4 + t;
        invS[nt] = inv_s[c]; invT[nt] = inv_s[64 + c]; invM[nt] = inv_s[128 + c];
    }
    float* pm = (float*)(sm + PM_OFF);
    #pragma unroll
    for (int mt = 0; mt < 4; ++mt) {
        #pragma unroll
        for (int h = 0; h < 2; ++h) {
            float Z0 = 0.f, Z1 = 0.f, Z2 = 0.f;
            float A[9] = {0.f, 0.f, 0.f, 0.f, 0.f, 0.f, 0.f, 0.f, 0.f};
            #pragma unroll
            for (int nt = 0; nt < 4; ++nt) {
                float Sr = acc[mt][nt][2*h], Tr = acc[mt][nt][2*h+1];
                float ps2 = Sr * invS[nt], pt = Tr * invT[nt], pv = (Sr + Tr) * invM[nt];
                float eS = __expf(ps2), eT = __expf(pt), eM = __expf(pv);
                Z0 += eS; Z1 += eT; Z2 += eM;
                A[0] += eS * ps2; A[1] += eS * pt; A[2] += eS * pv;
                A[3] += eT * ps2; A[4] += eT * pt; A[5] += eT * pv;
                A[6] += eM * ps2; A[7] += eM * pt; A[8] += eM * pv;
            }
            Z0 = qsum(Z0); Z1 = qsum(Z1); Z2 = qsum(Z2);
            #pragma unroll
            for (int i = 0; i < 9; ++i) A[i] = qsum(A[i]);
            if (t == 0) {
                int row = wm * 64 + mt * 16 + g + 8 * h;
                float* d = pm + (row * 4 + wn) * 12;
                d[0] = Z0; d[1] = Z1; d[2] = Z2;
                #pragma unroll
                for (int i = 0; i < 9; ++i) d[3 + i] = A[i];
            }
        }
    }
    __syncthreads();

    float Jr = 0.f;
    if (tid < 128) {
        float v[12];
        #pragma unroll
        for (int i = 0; i < 12; ++i)
            v[i] = pm[(tid * 4 + 0) * 12 + i] + pm[(tid * 4 + 1) * 12 + i]
                 + pm[(tid * 4 + 2) * 12 + i] + pm[(tid * 4 + 3) * 12 + i];
        Jr = __fdividef(2.f * v[3] - v[4] - v[5], v[0])
           + __fdividef(2.f * v[7] - v[6] - v[8], v[1])
           + __fdividef(2.f * v[11] - v[9] - v[10], v[2]);
    }
    #pragma unroll
    for (int o = 16; o; o >>= 1) Jr += __shfl_xor_sync(~0u, Jr, o);
    if (lane == 0) red[w] = Jr;
    __syncthreads();
    if (tid == 0) {
        float bs = 0.f;
        #pragma unroll
        for (int i = 0; i < 8; ++i) bs += red[i];
        atomicAdd(&g_acc, (double)bs);
    }
}

__global__ void k_final(float* out) {
    out[0] = (float)(g_acc * (0.5 / (3.0 * 131072.0 * 64.0)));
}

extern "C" void kernel_launch(void* const* d_in, const int* in_sizes, int n_in,
                              void* d_out, int out_size) {
    const float* src = (const float*)d_in[0];
    const float* trg = (const float*)d_in[1];
    const int*   sl  = (const int*)d_in[2];
    const int*   tl  = (const int*)d_in[3];

    cudaFuncSetAttribute(k_segsum, cudaFuncAttributeMaxDynamicSharedMemorySize, 106496);
    cudaFuncSetAttribute(k_main,   cudaFuncAttributeMaxDynamicSharedMemorySize, SMEM_MAIN);

    k_zero<<<1, 256>>>(sl);
    k_segsum<<<512, 128, 106496>>>(src, trg, sl, tl);
    k_red<<<256, 256>>>();
    k_prep<<<64, 512>>>();
    k_main<<<1024, 256, SMEM_MAIN>>>();
    k_final<<<1, 1>>>((float*)d_out);
}

// round 12
// speedup vs baseline: 2.8732x; 1.0764x over previous
#include <cuda_runtime.h>
#include <cuda_bf16.h>
#include <cstdint>

#define NCLS 64
#define DIM 256
#define NROWS 65536
#define TOTROWS 131072

__device__ __align__(16) __nv_bfloat16 g_featbf[(size_t)TOTROWS * DIM];
__device__ __align__(16) __nv_bfloat162 g_scratch_bf[2 * 256 * NCLS * 128]; // 16MB
__device__ __align__(16) float g_wpart[4096 * 16 * 8];   // 2MB partials, elem-major
__device__ int    g_icnt[2][NCLS];
__device__ __align__(16) __nv_bfloat16 g_wbf[4 * 8192];  // W bf16 swizzled, cols interleaved
__device__ float  g_inv[3 * NCLS];
__device__ double g_acc;
__device__ int    g_lstride;

__device__ __forceinline__ uint32_t smem_u32(const void* p) {
    uint32_t r;
    asm("{ .reg .u64 t; cvta.to.shared.u64 t, %1; cvt.u32.u64 %0, t; }" : "=r"(r) : "l"(p));
    return r;
}
__device__ __forceinline__ void cpa16(uint32_t dst, const void* src) {
    asm volatile("cp.async.cg.shared.global [%0], [%1], 16;" :: "r"(dst), "l"(src));
}
__device__ __forceinline__ void cp_commit() { asm volatile("cp.async.commit_group;"); }
template<int N> __device__ __forceinline__ void cp_wait() {
    asm volatile("cp.async.wait_group %0;" :: "n"(N));
}
__device__ __forceinline__ uint32_t lds_u32(uint32_t a) {
    uint32_t v; asm volatile("ld.shared.b32 %0, [%1];" : "=r"(v) : "r"(a)); return v;
}
__device__ __forceinline__ void mma_bf16(float* d, const uint32_t* a, const uint32_t* b) {
    asm volatile("mma.sync.aligned.m16n8k16.row.col.f32.bf16.bf16.f32 "
        "{%0,%1,%2,%3}, {%4,%5,%6,%7}, {%8,%9}, {%0,%1,%2,%3};"
        : "+f"(d[0]), "+f"(d[1]), "+f"(d[2]), "+f"(d[3])
        : "r"(a[0]), "r"(a[1]), "r"(a[2]), "r"(a[3]), "r"(b[0]), "r"(b[1]));
}
__device__ __forceinline__ float qsum(float v) {
    v += __shfl_xor_sync(~0u, v, 1);
    v += __shfl_xor_sync(~0u, v, 2);
    return v;
}
__device__ __forceinline__ float ex2(float x) {
    float y; asm("ex2.approx.ftz.f32 %0, %1;" : "=f"(y) : "f"(x)); return y;
}

// ---- zero + label-dtype detect (merged) ----
__global__ void k_zero(const int* __restrict__ lbl) {
    int i = threadIdx.x;
    if (i < 128) ((int*)g_icnt)[i] = 0;
    if (i == 128) g_acc = 0.0;
    if (i == 129) {
        bool oz = true;
        #pragma unroll
        for (int j = 0; j < 64; ++j) oz &= (lbl[2 * j + 1] == 0);
        g_lstride = oz ? 2 : 1;
    }
}

// ---- segment sums + label counts: 512 blocks x 128 thr, 5-slot cp.async ring ----
__global__ void __launch_bounds__(128) k_segsum(const float* __restrict__ src,
        const float* __restrict__ trg, const int* __restrict__ sl,
        const int* __restrict__ tl) {
    extern __shared__ float smf[];
    float2* bins = (float2*)(smf + 5 * 2048);
    __shared__ int lbl_s[256];
    const int feat = blockIdx.x >> 8, chunk = blockIdx.x & 255;
    const float* fp = feat ? trg : src;
    const int*   lp = feat ? tl : sl;
    const int ls = g_lstride, tid = threadIdx.x;
    const int base = chunk * 256;
    const uint32_t sbs = smem_u32(smf);
    const float* fin = fp + (size_t)base * DIM;

    #pragma unroll
    for (int s = 0; s < 4; ++s) {
        #pragma unroll
        for (int j = 0; j < 4; ++j) {
            int uu = j * 128 + tid;
            cpa16(sbs + (uint32_t)(s * 8192 + uu * 16), fin + (size_t)s * 2048 + uu * 4);
        }
        cp_commit();
    }

    lbl_s[tid]       = lp[(base + tid) * ls] & 63;
    lbl_s[tid + 128] = lp[(base + tid + 128) * ls] & 63;
    #pragma unroll
    for (int c = 0; c < NCLS; ++c) bins[c * 128 + tid] = make_float2(0.f, 0.f);

    __nv_bfloat162* outb = (__nv_bfloat162*)g_featbf
                         + (size_t)(feat * NROWS + base) * 128 + tid;

    int ws = 4, ps = 0;
    for (int s = 0; s < 32; ++s) {
        if (s + 4 < 32) {
            #pragma unroll
            for (int j = 0; j < 4; ++j) {
                int uu = j * 128 + tid;
                cpa16(sbs + (uint32_t)(ws * 8192 + uu * 16),
                      fin + (size_t)(s + 4) * 2048 + uu * 4);
            }
        }
        cp_commit();
        cp_wait<4>();
        __syncthreads();

        const float2* sp = (const float2*)(smf + ps * 2048);
        #pragma unroll
        for (int i = 0; i < 8; ++i) {
            int r = s * 8 + i;
            float2 v = sp[i * 128 + tid];
            outb[(size_t)r * 128] = __floats2bfloat162_rn(v.x, v.y);
            int c = lbl_s[r];
            float2 b = bins[c * 128 + tid];
            b.x += v.x; b.y += v.y;
            bins[c * 128 + tid] = b;
        }
        __syncthreads();
        if (++ws == 5) ws = 0;
        if (++ps == 5) ps = 0;
    }

    if (tid < NCLS) {
        int cnt = 0;
        #pragma unroll 8
        for (int r = 0; r < 256; ++r) cnt += (lbl_s[r] == tid);
        atomicAdd(&g_icnt[feat][tid], cnt);
    }

    __nv_bfloat162* sc = g_scratch_bf + ((size_t)(feat * 256 + chunk) * NCLS) * 128 + tid;
    #pragma unroll 8
    for (int c = 0; c < NCLS; ++c)
        sc[c * 128] = __float22bfloat162_rn(bins[c * 128 + tid]);
}

// ---- reduce stage 1: 16 partials, uint4 loads, elem-major output ----
__global__ void __launch_bounds__(256) k_red() {
    int q = blockIdx.x * 256 + threadIdx.x;    // 0..65535
    int p = q >> 12;
    int rem = q & 4095;
    int cls = rem >> 5, quad = rem & 31;
    int feat = cls >> 6, c = cls & 63;
    const uint4* srcp = (const uint4*)(g_scratch_bf
        + ((size_t)((feat * 256 + p * 16) * NCLS + c)) * 128 + quad * 4);
    float s[8] = {0.f, 0.f, 0.f, 0.f, 0.f, 0.f, 0.f, 0.f};
    #pragma unroll 16
    for (int ch = 0; ch < 16; ++ch) {
        uint4 v = srcp[(size_t)ch * 2048];
        const __nv_bfloat162* pv = (const __nv_bfloat162*)&v;
        #pragma unroll
        for (int t2 = 0; t2 < 4; ++t2) {
            float2 f = __bfloat1622float2(pv[t2]);
            s[2 * t2] += f.x; s[2 * t2 + 1] += f.y;
        }
    }
    float4* d = (float4*)(g_wpart + (size_t)rem * 128 + p * 8);
    d[0] = make_float4(s[0], s[1], s[2], s[3]);
    d[1] = make_float4(s[4], s[5], s[6], s[7]);
}

// ---- reduce stage 2 (vectorized): float4 partial loads, 8B bf16 writes ----
__global__ void __launch_bounds__(512) k_prep() {
    int idx = blockIdx.x * 512 + threadIdx.x;  // 0..8191
    int ef = idx >> 1, jh = idx & 1;
    float4 s = make_float4(0.f, 0.f, 0.f, 0.f);
    const float4* pp = (const float4*)(g_wpart + (size_t)ef * 128 + jh * 4);
    #pragma unroll 16
    for (int p = 0; p < 16; ++p) {
        float4 v = pp[p * 2];
        s.x += v.x; s.y += v.y; s.z += v.z; s.w += v.w;
    }
    int cls = ef >> 5, quad = ef & 31;
    int nc = ((cls & 63) << 1) | (cls >> 6);
    int k0 = quad * 8;                          // u = quad&7 same for all 4 elems
    int kc = k0 >> 6, u = (k0 >> 3) & 7;
    __nv_bfloat16* dst = g_wbf + kc * 8192 + (nc * 8 + (u ^ (nc & 7))) * 8 + jh * 4;
    __nv_bfloat162* d2 = (__nv_bfloat162*)dst;
    d2[0] = __floats2bfloat162_rn(s.x, s.y);
    d2[1] = __floats2bfloat162_rn(s.z, s.w);
    if (idx < 3 * NCLS) {
        int which = idx >> 6, c2 = idx & 63;
        float cs = (float)g_icnt[0][c2], ct = (float)g_icnt[1][c2];
        g_inv[idx] = (which == 0) ? 1.f / cs : (which == 1) ? 1.f / ct : 1.f / (cs + ct);
    }
}

// ---- fused bf16 GEMM + combined-moment KL: 1024 blocks x 256 thr ----
#define WB_OFF 0
#define FB_OFF 65536
#define PM_OFF 65536
#define INV_OFF 98304
#define RED_OFF 99072
#define SMEM_MAIN 99104

__global__ void __launch_bounds__(256, 2) k_main() {
    extern __shared__ unsigned char sm[];
    float* inv_s = (float*)(sm + INV_OFF);
    float* red   = (float*)(sm + RED_OFF);
    const uint32_t sb = smem_u32(sm);
    const int tid = threadIdx.x, w = tid >> 5, lane = tid & 31;
    const int g = lane >> 2, t = lane & 3;
    const int wm = w >> 2, wn = w & 3;

    if (tid < 192) inv_s[tid] = g_inv[tid];

    #pragma unroll
    for (int j = 0; j < 16; ++j) {
        int uu = j * 256 + tid;
        cpa16(sb + WB_OFF + uu * 16, g_wbf + uu * 8);
    }
    cp_commit();

    const __nv_bfloat16* frow = g_featbf + (size_t)blockIdx.x * 128 * DIM;
    #pragma unroll
    for (int j = 0; j < 4; ++j) {
        int uu = j * 256 + tid, row = uu >> 3, u = uu & 7;
        cpa16(sb + FB_OFF + (uint32_t)(row * 8 + (u ^ (row & 7))) * 16,
              frow + (size_t)row * DIM + u * 8);
    }
    cp_commit();

    float acc[4][4][4];
    #pragma unroll
    for (int x = 0; x < 4; ++x)
        #pragma unroll
        for (int y = 0; y < 4; ++y)
            #pragma unroll
            for (int z = 0; z < 4; ++z) acc[x][y][z] = 0.f;

    #pragma unroll
    for (int kc = 0; kc < 4; ++kc) {
        if (kc < 3) {
            int nb = (kc + 1) & 1;
            #pragma unroll
            for (int j = 0; j < 4; ++j) {
                int uu = j * 256 + tid, row = uu >> 3, u = uu & 7;
                cpa16(sb + FB_OFF + nb * 16384 + (uint32_t)(row * 8 + (u ^ (row & 7))) * 16,
                      frow + (size_t)row * DIM + (kc + 1) * 64 + u * 8);
            }
            cp_commit();
            cp_wait<1>();
        } else {
            cp_wait<0>();
        }
        __syncthreads();

        const uint32_t fb = sb + FB_OFF + (kc & 1) * 16384;
        const uint32_t wb = sb + WB_OFF + kc * 16384;
        #pragma unroll
        for (int s = 0; s < 4; ++s) {
            uint32_t a[4][4], b[4][2];
            #pragma unroll
            for (int mt = 0; mt < 4; ++mt) {
                int r0 = wm * 64 + mt * 16 + g, r1 = r0 + 8;
                a[mt][0] = lds_u32(fb + (uint32_t)(r0 * 8 + ((2*s)   ^ (r0 & 7))) * 16 + 4 * t);
                a[mt][1] = lds_u32(fb + (uint32_t)(r1 * 8 + ((2*s)   ^ (r1 & 7))) * 16 + 4 * t);
                a[mt][2] = lds_u32(fb + (uint32_t)(r0 * 8 + ((2*s+1) ^ (r0 & 7))) * 16 + 4 * t);
                a[mt][3] = lds_u32(fb + (uint32_t)(r1 * 8 + ((2*s+1) ^ (r1 & 7))) * 16 + 4 * t);
            }
            #pragma unroll
            for (int nt = 0; nt < 4; ++nt) {
                int cn = wn * 32 + nt * 8 + g;
                b[nt][0] = lds_u32(wb + (uint32_t)(cn * 8 + ((2*s)   ^ (cn & 7))) * 16 + 4 * t);
                b[nt][1] = lds_u32(wb + (uint32_t)(cn * 8 + ((2*s+1) ^ (cn & 7))) * 16 + 4 * t);
            }
            #pragma unroll
            for (int mt = 0; mt < 4; ++mt)
                #pragma unroll
                for (int nt = 0; nt < 4; ++nt)
                    mma_bf16(acc[mt][nt], a[mt], b[nt]);
        }
        __syncthreads();
    }

    // ---- epilogue: combined moments in log2 domain ----
    const float LOG2E = 1.44269504f;
    float invS[4], invT[4], invM[4];
    #pragma unroll
    for (int nt = 0; nt < 4; ++nt) {
        int c = wn * 16 + nt * 4 + t;
        invS[nt] = inv_s[c] * LOG2E;
        invT[nt] = inv_s[64 + c] * LOG2E;
        invM[nt] = inv_s[128 + c] * LOG2E;
    }
    float* pm = (float*)(sm + PM_OFF);
    #pragma unroll
    for (int mt = 0; mt < 4; ++mt) {
        #pragma unroll
        for (int h = 0; h < 2; ++h) {
            float Z0 = 0.f, Z1 = 0.f, Z2 = 0.f;
            float B0 = 0.f, B1 = 0.f, B2 = 0.f;
            #pragma unroll
            for (int nt = 0; nt < 4; ++nt) {
                float Sr = acc[mt][nt][2*h], Tr = acc[mt][nt][2*h+1];
                float ps2 = Sr * invS[nt], pt = Tr * invT[nt], pv = (Sr + Tr) * invM[nt];
                float eS = ex2(ps2), eT = ex2(pt), eM = ex2(pv);
                float dw = ps2 - pt, dx = ps2 - pv, dy = pt - pv;
                Z0 += eS; Z1 += eT; Z2 += eM;
                B0 += eS * (dw + dx);
                B1 += eT * (dy - dw);
                B2 -= eM * (dx + dy);
            }
            Z0 = qsum(Z0); Z1 = qsum(Z1); Z2 = qsum(Z2);
            B0 = qsum(B0); B1 = qsum(B1); B2 = qsum(B2);
            if (t == 0) {
                int row = wm * 64 + mt * 16 + g + 8 * h;
                float* d = pm + (row * 4 + wn) * 6;
                d[0] = Z0; d[1] = Z1; d[2] = Z2;
                d[3] = B0; d[4] = B1; d[5] = B2;
            }
        }
    }
    __syncthreads();

    float Jr = 0.f;
    if (tid < 128) {
        float v[6];
        #pragma unroll
        for (int i = 0; i < 6; ++i)
            v[i] = pm[(tid * 4 + 0) * 6 + i] + pm[(tid * 4 + 1) * 6 + i]
                 + pm[(tid * 4 + 2) * 6 + i] + pm[(tid * 4 + 3) * 6 + i];
        Jr = (__fdividef(v[3], v[0]) + __fdividef(v[4], v[1])
            + __fdividef(v[5], v[2])) * 0.69314718f;   // ln2: undo log2 scaling
    }
    #pragma unroll
    for (int o = 16; o; o >>= 1) Jr += __shfl_xor_sync(~0u, Jr, o);
    if (lane == 0) red[w] = Jr;
    __syncthreads();
    if (tid == 0) {
        float bs = 0.f;
        #pragma unroll
        for (int i = 0; i < 8; ++i) bs += red[i];
        atomicAdd(&g_acc, (double)bs);
    }
}

__global__ void k_final(float* out) {
    out[0] = (float)(g_acc * (0.5 / (3.0 * 131072.0 * 64.0)));
}

extern "C" void kernel_launch(void* const* d_in, const int* in_sizes, int n_in,
                              void* d_out, int out_size) {
    const float* src = (const float*)d_in[0];
    const float* trg = (const float*)d_in[1];
    const int*   sl  = (const int*)d_in[2];
    const int*   tl  = (const int*)d_in[3];

    cudaFuncSetAttribute(k_segsum, cudaFuncAttributeMaxDynamicSharedMemorySize, 106496);
    cudaFuncSetAttribute(k_main,   cudaFuncAttributeMaxDynamicSharedMemorySize, SMEM_MAIN);

    k_zero<<<1, 256>>>(sl);
    k_segsum<<<512, 128, 106496>>>(src, trg, sl, tl);
    k_red<<<256, 256>>>();
    k_prep<<<16, 512>>>();
    k_main<<<1024, 256, SMEM_MAIN>>>();
    k_final<<<1, 1>>>((float*)d_out);
}

// round 13
// speedup vs baseline: 2.9275x; 1.0189x over previous
#include <cuda_runtime.h>
#include <cuda_bf16.h>
#include <cstdint>

#define NCLS 64
#define DIM 256
#define NROWS 65536
#define TOTROWS 131072

__device__ __align__(16) __nv_bfloat16 g_featbf[(size_t)TOTROWS * DIM];
__device__ __align__(16) __nv_bfloat162 g_scratch_bf[2 * 256 * NCLS * 128]; // 16MB
__device__ __align__(16) float g_wpart[4096 * 16 * 8];   // 2MB partials, elem-major
__device__ int    g_icnt[2][NCLS];
__device__ __align__(16) __nv_bfloat16 g_wbf[4 * 8192];  // W bf16 swizzled, cols interleaved
__device__ float  g_inv[3 * NCLS];
__device__ double g_acc;
__device__ int    g_lstride;

__device__ __forceinline__ uint32_t smem_u32(const void* p) {
    uint32_t r;
    asm("{ .reg .u64 t; cvta.to.shared.u64 t, %1; cvt.u32.u64 %0, t; }" : "=r"(r) : "l"(p));
    return r;
}
__device__ __forceinline__ void cpa16(uint32_t dst, const void* src) {
    asm volatile("cp.async.cg.shared.global [%0], [%1], 16;" :: "r"(dst), "l"(src));
}
__device__ __forceinline__ void cp_commit() { asm volatile("cp.async.commit_group;"); }
template<int N> __device__ __forceinline__ void cp_wait() {
    asm volatile("cp.async.wait_group %0;" :: "n"(N));
}
__device__ __forceinline__ uint32_t lds_u32(uint32_t a) {
    uint32_t v; asm volatile("ld.shared.b32 %0, [%1];" : "=r"(v) : "r"(a)); return v;
}
__device__ __forceinline__ void mma_bf16(float* d, const uint32_t* a, const uint32_t* b) {
    asm volatile("mma.sync.aligned.m16n8k16.row.col.f32.bf16.bf16.f32 "
        "{%0,%1,%2,%3}, {%4,%5,%6,%7}, {%8,%9}, {%0,%1,%2,%3};"
        : "+f"(d[0]), "+f"(d[1]), "+f"(d[2]), "+f"(d[3])
        : "r"(a[0]), "r"(a[1]), "r"(a[2]), "r"(a[3]), "r"(b[0]), "r"(b[1]));
}
__device__ __forceinline__ float qsum(float v) {
    v += __shfl_xor_sync(~0u, v, 1);
    v += __shfl_xor_sync(~0u, v, 2);
    return v;
}
__device__ __forceinline__ float ex2(float x) {
    float y; asm("ex2.approx.ftz.f32 %0, %1;" : "=f"(y) : "f"(x)); return y;
}

// ---- zero + label-dtype detect (merged) ----
__global__ void k_zero(const int* __restrict__ lbl) {
    int i = threadIdx.x;
    if (i < 128) ((int*)g_icnt)[i] = 0;
    if (i == 128) g_acc = 0.0;
    if (i == 129) {
        bool oz = true;
        #pragma unroll
        for (int j = 0; j < 64; ++j) oz &= (lbl[2 * j + 1] == 0);
        g_lstride = oz ? 2 : 1;
    }
}

// ---- segment sums: 512 blocks x 128 thr; per-warp independent 5-slot rings ----
// warp w owns cols [w*64, w*64+64); NO barriers in the streaming loop.
__global__ void __launch_bounds__(128) k_segsum(const float* __restrict__ src,
        const float* __restrict__ trg, const int* __restrict__ sl,
        const int* __restrict__ tl) {
    extern __shared__ float smf[];             // [4 warps][5 slots][512 f] ring (40KB) + bins (64KB)
    float2* bins = (float2*)(smf + 4 * 5 * 512);
    __shared__ int lbl_s[256];
    const int feat = blockIdx.x >> 8, chunk = blockIdx.x & 255;
    const float* fp = feat ? trg : src;
    const int*   lp = feat ? tl : sl;
    const int ls = g_lstride, tid = threadIdx.x;
    const int lane = tid & 31, w = tid >> 5;
    const int base = chunk * 256;
    const uint32_t ringb = smem_u32(smf) + w * 10240;   // warp's 5x2KB ring

    const float* fin = fp + (size_t)base * DIM + w * 64;  // warp's column slice

    // prologue: 4 stages in flight (per-warp groups)
    #pragma unroll
    for (int s = 0; s < 4; ++s) {
        #pragma unroll
        for (int j = 0; j < 4; ++j) {
            int uu = j * 32 + lane;            // 0..127 = row*16 + unit
            int row = uu >> 4, c16 = uu & 15;
            cpa16(ringb + (uint32_t)(s * 2048 + uu * 16),
                  fin + (size_t)(s * 8 + row) * DIM + c16 * 4);
        }
        cp_commit();
    }

    lbl_s[tid]       = lp[(base + tid) * ls] & 63;
    lbl_s[tid + 128] = lp[(base + tid + 128) * ls] & 63;
    #pragma unroll
    for (int c = 0; c < NCLS; ++c) bins[c * 128 + tid] = make_float2(0.f, 0.f);
    __syncthreads();                            // labels visible; only sync in kernel

    __nv_bfloat162* outb = (__nv_bfloat162*)g_featbf
                         + (size_t)(feat * NROWS + base) * 128 + tid;

    int ws = 4, ps = 0;
    for (int s = 0; s < 32; ++s) {
        if (s + 4 < 32) {
            #pragma unroll
            for (int j = 0; j < 4; ++j) {
                int uu = j * 32 + lane;
                int row = uu >> 4, c16 = uu & 15;
                cpa16(ringb + (uint32_t)(ws * 2048 + uu * 16),
                      fin + (size_t)((s + 4) * 8 + row) * DIM + c16 * 4);
            }
        }
        cp_commit();                            // possibly empty; keeps wait math exact
        cp_wait<4>();                           // per-thread: no barrier needed

        const float2* sp = (const float2*)(smf + (w * 5 + ps) * 512);
        #pragma unroll
        for (int i = 0; i < 8; ++i) {
            int r = s * 8 + i;
            float2 v = sp[i * 32 + lane];
            outb[(size_t)r * 128] = __floats2bfloat162_rn(v.x, v.y);
            int c = lbl_s[r];
            float2 b = bins[c * 128 + tid];
            b.x += v.x; b.y += v.y;
            bins[c * 128 + tid] = b;
        }
        if (++ws == 5) ws = 0;
        if (++ps == 5) ps = 0;
    }

    if (tid < NCLS) {                           // fused label histogram
        int cnt = 0;
        #pragma unroll 8
        for (int r = 0; r < 256; ++r) cnt += (lbl_s[r] == tid);
        atomicAdd(&g_icnt[feat][tid], cnt);
    }

    __nv_bfloat162* sc = g_scratch_bf + ((size_t)(feat * 256 + chunk) * NCLS) * 128 + tid;
    #pragma unroll 8
    for (int c = 0; c < NCLS; ++c)
        sc[c * 128] = __float22bfloat162_rn(bins[c * 128 + tid]);
}

// ---- reduce stage 1: 16 partials, uint4 loads, elem-major output ----
__global__ void __launch_bounds__(256) k_red() {
    int q = blockIdx.x * 256 + threadIdx.x;    // 0..65535
    int p = q >> 12;
    int rem = q & 4095;
    int cls = rem >> 5, quad = rem & 31;
    int feat = cls >> 6, c = cls & 63;
    const uint4* srcp = (const uint4*)(g_scratch_bf
        + ((size_t)((feat * 256 + p * 16) * NCLS + c)) * 128 + quad * 4);
    float s[8] = {0.f, 0.f, 0.f, 0.f, 0.f, 0.f, 0.f, 0.f};
    #pragma unroll 16
    for (int ch = 0; ch < 16; ++ch) {
        uint4 v = srcp[(size_t)ch * 2048];
        const __nv_bfloat162* pv = (const __nv_bfloat162*)&v;
        #pragma unroll
        for (int t2 = 0; t2 < 4; ++t2) {
            float2 f = __bfloat1622float2(pv[t2]);
            s[2 * t2] += f.x; s[2 * t2 + 1] += f.y;
        }
    }
    float4* d = (float4*)(g_wpart + (size_t)rem * 128 + p * 8);
    d[0] = make_float4(s[0], s[1], s[2], s[3]);
    d[1] = make_float4(s[4], s[5], s[6], s[7]);
}

// ---- reduce stage 2: 64 blocks x 128 thr (spread across SMs) ----
__global__ void __launch_bounds__(128) k_prep() {
    int idx = blockIdx.x * 128 + threadIdx.x;  // 0..8191
    int ef = idx >> 1, jh = idx & 1;
    float4 s = make_float4(0.f, 0.f, 0.f, 0.f);
    const float4* pp = (const float4*)(g_wpart + (size_t)ef * 128 + jh * 4);
    #pragma unroll 16
    for (int p = 0; p < 16; ++p) {
        float4 v = pp[p * 2];
        s.x += v.x; s.y += v.y; s.z += v.z; s.w += v.w;
    }
    int cls = ef >> 5, quad = ef & 31;
    int nc = ((cls & 63) << 1) | (cls >> 6);
    int k0 = quad * 8;
    int kc = k0 >> 6, u = (k0 >> 3) & 7;
    __nv_bfloat162* d2 = (__nv_bfloat162*)(g_wbf + kc * 8192
                        + (nc * 8 + (u ^ (nc & 7))) * 8 + jh * 4);
    d2[0] = __floats2bfloat162_rn(s.x, s.y);
    d2[1] = __floats2bfloat162_rn(s.z, s.w);
    if (idx < 3 * NCLS) {
        int which = idx >> 6, c2 = idx & 63;
        float cs = (float)g_icnt[0][c2], ct = (float)g_icnt[1][c2];
        g_inv[idx] = (which == 0) ? 1.f / cs : (which == 1) ? 1.f / ct : 1.f / (cs + ct);
    }
}

// ---- fused bf16 GEMM + combined-moment KL (R12 winner, unchanged) ----
#define WB_OFF 0
#define FB_OFF 65536
#define PM_OFF 65536
#define INV_OFF 98304
#define RED_OFF 99072
#define SMEM_MAIN 99104

__global__ void __launch_bounds__(256, 2) k_main() {
    extern __shared__ unsigned char sm[];
    float* inv_s = (float*)(sm + INV_OFF);
    float* red   = (float*)(sm + RED_OFF);
    const uint32_t sb = smem_u32(sm);
    const int tid = threadIdx.x, w = tid >> 5, lane = tid & 31;
    const int g = lane >> 2, t = lane & 3;
    const int wm = w >> 2, wn = w & 3;

    if (tid < 192) inv_s[tid] = g_inv[tid];

    #pragma unroll
    for (int j = 0; j < 16; ++j) {
        int uu = j * 256 + tid;
        cpa16(sb + WB_OFF + uu * 16, g_wbf + uu * 8);
    }
    cp_commit();

    const __nv_bfloat16* frow = g_featbf + (size_t)blockIdx.x * 128 * DIM;
    #pragma unroll
    for (int j = 0; j < 4; ++j) {
        int uu = j * 256 + tid, row = uu >> 3, u = uu & 7;
        cpa16(sb + FB_OFF + (uint32_t)(row * 8 + (u ^ (row & 7))) * 16,
              frow + (size_t)row * DIM + u * 8);
    }
    cp_commit();

    float acc[4][4][4];
    #pragma unroll
    for (int x = 0; x < 4; ++x)
        #pragma unroll
        for (int y = 0; y < 4; ++y)
            #pragma unroll
            for (int z = 0; z < 4; ++z) acc[x][y][z] = 0.f;

    #pragma unroll
    for (int kc = 0; kc < 4; ++kc) {
        if (kc < 3) {
            int nb = (kc + 1) & 1;
            #pragma unroll
            for (int j = 0; j < 4; ++j) {
                int uu = j * 256 + tid, row = uu >> 3, u = uu & 7;
                cpa16(sb + FB_OFF + nb * 16384 + (uint32_t)(row * 8 + (u ^ (row & 7))) * 16,
                      frow + (size_t)row * DIM + (kc + 1) * 64 + u * 8);
            }
            cp_commit();
            cp_wait<1>();
        } else {
            cp_wait<0>();
        }
        __syncthreads();

        const uint32_t fb = sb + FB_OFF + (kc & 1) * 16384;
        const uint32_t wb = sb + WB_OFF + kc * 16384;
        #pragma unroll
        for (int s = 0; s < 4; ++s) {
            uint32_t a[4][4], b[4][2];
            #pragma unroll
            for (int mt = 0; mt < 4; ++mt) {
                int r0 = wm * 64 + mt * 16 + g, r1 = r0 + 8;
                a[mt][0] = lds_u32(fb + (uint32_t)(r0 * 8 + ((2*s)   ^ (r0 & 7))) * 16 + 4 * t);
                a[mt][1] = lds_u32(fb + (uint32_t)(r1 * 8 + ((2*s)   ^ (r1 & 7))) * 16 + 4 * t);
                a[mt][2] = lds_u32(fb + (uint32_t)(r0 * 8 + ((2*s+1) ^ (r0 & 7))) * 16 + 4 * t);
                a[mt][3] = lds_u32(fb + (uint32_t)(r1 * 8 + ((2*s+1) ^ (r1 & 7))) * 16 + 4 * t);
            }
            #pragma unroll
            for (int nt = 0; nt < 4; ++nt) {
                int cn = wn * 32 + nt * 8 + g;
                b[nt][0] = lds_u32(wb + (uint32_t)(cn * 8 + ((2*s)   ^ (cn & 7))) * 16 + 4 * t);
                b[nt][1] = lds_u32(wb + (uint32_t)(cn * 8 + ((2*s+1) ^ (cn & 7))) * 16 + 4 * t);
            }
            #pragma unroll
            for (int mt = 0; mt < 4; ++mt)
                #pragma unroll
                for (int nt = 0; nt < 4; ++nt)
                    mma_bf16(acc[mt][nt], a[mt], b[nt]);
        }
        __syncthreads();
    }

    const float LOG2E = 1.44269504f;
    float invS[4], invT[4], invM[4];
    #pragma unroll
    for (int nt = 0; nt < 4; ++nt) {
        int c = wn * 16 + nt * 4 + t;
        invS[nt] = inv_s[c] * LOG2E;
        invT[nt] = inv_s[64 + c] * LOG2E;
        invM[nt] = inv_s[128 + c] * LOG2E;
    }
    float* pm = (float*)(sm + PM_OFF);
    #pragma unroll
    for (int mt = 0; mt < 4; ++mt) {
        #pragma unroll
        for (int h = 0; h < 2; ++h) {
            float Z0 = 0.f, Z1 = 0.f, Z2 = 0.f;
            float B0 = 0.f, B1 = 0.f, B2 = 0.f;
            #pragma unroll
            for (int nt = 0; nt < 4; ++nt) {
                float Sr = acc[mt][nt][2*h], Tr = acc[mt][nt][2*h+1];
                float ps2 = Sr * invS[nt], pt = Tr * invT[nt], pv = (Sr + Tr) * invM[nt];
                float eS = ex2(ps2), eT = ex2(pt), eM = ex2(pv);
                float dw = ps2 - pt, dx = ps2 - pv, dy = pt - pv;
                Z0 += eS; Z1 += eT; Z2 += eM;
                B0 += eS * (dw + dx);
                B1 += eT * (dy - dw);
                B2 -= eM * (dx + dy);
            }
            Z0 = qsum(Z0); Z1 = qsum(Z1); Z2 = qsum(Z2);
            B0 = qsum(B0); B1 = qsum(B1); B2 = qsum(B2);
            if (t == 0) {
                int row = wm * 64 + mt * 16 + g + 8 * h;
                float* d = pm + (row * 4 + wn) * 6;
                d[0] = Z0; d[1] = Z1; d[2] = Z2;
                d[3] = B0; d[4] = B1; d[5] = B2;
            }
        }
    }
    __syncthreads();

    float Jr = 0.f;
    if (tid < 128) {
        float v[6];
        #pragma unroll
        for (int i = 0; i < 6; ++i)
            v[i] = pm[(tid * 4 + 0) * 6 + i] + pm[(tid * 4 + 1) * 6 + i]
                 + pm[(tid * 4 + 2) * 6 + i] + pm[(tid * 4 + 3) * 6 + i];
        Jr = (__fdividef(v[3], v[0]) + __fdividef(v[4], v[1])
            + __fdividef(v[5], v[2])) * 0.69314718f;
    }
    #pragma unroll
    for (int o = 16; o; o >>= 1) Jr += __shfl_xor_sync(~0u, Jr, o);
    if (lane == 0) red[w] = Jr;
    __syncthreads();
    if (tid == 0) {
        float bs = 0.f;
        #pragma unroll
        for (int i = 0; i < 8; ++i) bs += red[i];
        atomicAdd(&g_acc, (double)bs);
    }
}

__global__ void k_final(float* out) {
    out[0] = (float)(g_acc * (0.5 / (3.0 * 131072.0 * 64.0)));
}

extern "C" void kernel_launch(void* const* d_in, const int* in_sizes, int n_in,
                              void* d_out, int out_size) {
    const float* src = (const float*)d_in[0];
    const float* trg = (const float*)d_in[1];
    const int*   sl  = (const int*)d_in[2];
    const int*   tl  = (const int*)d_in[3];

    cudaFuncSetAttribute(k_segsum, cudaFuncAttributeMaxDynamicSharedMemorySize, 106496);
    cudaFuncSetAttribute(k_main,   cudaFuncAttributeMaxDynamicSharedMemorySize, SMEM_MAIN);

    k_zero<<<1, 256>>>(sl);
    k_segsum<<<512, 128, 106496>>>(src, trg, sl, tl);
    k_red<<<256, 256>>>();
    k_prep<<<64, 128>>>();
    k_main<<<1024, 256, SMEM_MAIN>>>();
    k_final<<<1, 1>>>((float*)d_out);
}

// round 14
// speedup vs baseline: 2.9520x; 1.0084x over previous
#include <cuda_runtime.h>
#include <cuda_bf16.h>
#include <cstdint>

#define NCLS 64
#define DIM 256
#define NROWS 65536
#define TOTROWS 131072

__device__ __align__(16) __nv_bfloat16 g_featbf[(size_t)TOTROWS * DIM];
__device__ __align__(16) __nv_bfloat162 g_scratch_bf[2 * 256 * NCLS * 128]; // 16MB
__device__ __align__(16) float g_wpart[4096 * 16 * 8];   // 2MB partials, elem-major
__device__ int    g_icnt[2][NCLS];
__device__ __align__(16) __nv_bfloat16 g_wbf[4 * 8192];  // W bf16 swizzled, cols interleaved
__device__ float  g_inv[3 * NCLS];
__device__ double g_acc;
__device__ int    g_lstride;

__device__ __forceinline__ uint32_t smem_u32(const void* p) {
    uint32_t r;
    asm("{ .reg .u64 t; cvta.to.shared.u64 t, %1; cvt.u32.u64 %0, t; }" : "=r"(r) : "l"(p));
    return r;
}
__device__ __forceinline__ void cpa16(uint32_t dst, const void* src) {
    asm volatile("cp.async.cg.shared.global [%0], [%1], 16;" :: "r"(dst), "l"(src));
}
__device__ __forceinline__ void cp_commit() { asm volatile("cp.async.commit_group;"); }
template<int N> __device__ __forceinline__ void cp_wait() {
    asm volatile("cp.async.wait_group %0;" :: "n"(N));
}
__device__ __forceinline__ uint32_t lds_u32(uint32_t a) {
    uint32_t v; asm volatile("ld.shared.b32 %0, [%1];" : "=r"(v) : "r"(a)); return v;
}
__device__ __forceinline__ void mma_bf16(float* d, const uint32_t* a, const uint32_t* b) {
    asm volatile("mma.sync.aligned.m16n8k16.row.col.f32.bf16.bf16.f32 "
        "{%0,%1,%2,%3}, {%4,%5,%6,%7}, {%8,%9}, {%0,%1,%2,%3};"
        : "+f"(d[0]), "+f"(d[1]), "+f"(d[2]), "+f"(d[3])
        : "r"(a[0]), "r"(a[1]), "r"(a[2]), "r"(a[3]), "r"(b[0]), "r"(b[1]));
}
__device__ __forceinline__ float qsum(float v) {
    v += __shfl_xor_sync(~0u, v, 1);
    v += __shfl_xor_sync(~0u, v, 2);
    return v;
}
__device__ __forceinline__ float ex2(float x) {
    float y; asm("ex2.approx.ftz.f32 %0, %1;" : "=f"(y) : "f"(x)); return y;
}

// ---- zero + label-dtype detect ----
__global__ void k_zero(const int* __restrict__ lbl) {
    int i = threadIdx.x;
    if (i < 128) ((int*)g_icnt)[i] = 0;
    if (i == 128) g_acc = 0.0;
    if (i == 129) {
        bool oz = true;
        #pragma unroll
        for (int j = 0; j < 64; ++j) oz &= (lbl[2 * j + 1] == 0);
        g_lstride = oz ? 2 : 1;
    }
}

// ---- segment sums (R13, at DRAM floor): per-warp rings, barrier-free loop ----
__global__ void __launch_bounds__(128) k_segsum(const float* __restrict__ src,
        const float* __restrict__ trg, const int* __restrict__ sl,
        const int* __restrict__ tl) {
    extern __shared__ float smf[];
    float2* bins = (float2*)(smf + 4 * 5 * 512);
    __shared__ int lbl_s[256];
    const int feat = blockIdx.x >> 8, chunk = blockIdx.x & 255;
    const float* fp = feat ? trg : src;
    const int*   lp = feat ? tl : sl;
    const int ls = g_lstride, tid = threadIdx.x;
    const int lane = tid & 31, w = tid >> 5;
    const int base = chunk * 256;
    const uint32_t ringb = smem_u32(smf) + w * 10240;
    const float* fin = fp + (size_t)base * DIM + w * 64;

    #pragma unroll
    for (int s = 0; s < 4; ++s) {
        #pragma unroll
        for (int j = 0; j < 4; ++j) {
            int uu = j * 32 + lane;
            int row = uu >> 4, c16 = uu & 15;
            cpa16(ringb + (uint32_t)(s * 2048 + uu * 16),
                  fin + (size_t)(s * 8 + row) * DIM + c16 * 4);
        }
        cp_commit();
    }

    lbl_s[tid]       = lp[(base + tid) * ls] & 63;
    lbl_s[tid + 128] = lp[(base + tid + 128) * ls] & 63;
    #pragma unroll
    for (int c = 0; c < NCLS; ++c) bins[c * 128 + tid] = make_float2(0.f, 0.f);
    __syncthreads();

    __nv_bfloat162* outb = (__nv_bfloat162*)g_featbf
                         + (size_t)(feat * NROWS + base) * 128 + tid;

    int ws = 4, ps = 0;
    for (int s = 0; s < 32; ++s) {
        if (s + 4 < 32) {
            #pragma unroll
            for (int j = 0; j < 4; ++j) {
                int uu = j * 32 + lane;
                int row = uu >> 4, c16 = uu & 15;
                cpa16(ringb + (uint32_t)(ws * 2048 + uu * 16),
                      fin + (size_t)((s + 4) * 8 + row) * DIM + c16 * 4);
            }
        }
        cp_commit();
        cp_wait<4>();

        const float2* sp = (const float2*)(smf + (w * 5 + ps) * 512);
        #pragma unroll
        for (int i = 0; i < 8; ++i) {
            int r = s * 8 + i;
            float2 v = sp[i * 32 + lane];
            outb[(size_t)r * 128] = __floats2bfloat162_rn(v.x, v.y);
            int c = lbl_s[r];
            float2 b = bins[c * 128 + tid];
            b.x += v.x; b.y += v.y;
            bins[c * 128 + tid] = b;
        }
        if (++ws == 5) ws = 0;
        if (++ps == 5) ps = 0;
    }

    if (tid < NCLS) {
        int cnt = 0;
        #pragma unroll 8
        for (int r = 0; r < 256; ++r) cnt += (lbl_s[r] == tid);
        atomicAdd(&g_icnt[feat][tid], cnt);
    }

    __nv_bfloat162* sc = g_scratch_bf + ((size_t)(feat * 256 + chunk) * NCLS) * 128 + tid;
    #pragma unroll 8
    for (int c = 0; c < NCLS; ++c)
        sc[c * 128] = __float22bfloat162_rn(bins[c * 128 + tid]);
}

// ---- reduce stage 1 (unchanged, at floor) ----
__global__ void __launch_bounds__(256) k_red() {
    int q = blockIdx.x * 256 + threadIdx.x;
    int p = q >> 12;
    int rem = q & 4095;
    int cls = rem >> 5, quad = rem & 31;
    int feat = cls >> 6, c = cls & 63;
    const uint4* srcp = (const uint4*)(g_scratch_bf
        + ((size_t)((feat * 256 + p * 16) * NCLS + c)) * 128 + quad * 4);
    float s[8] = {0.f, 0.f, 0.f, 0.f, 0.f, 0.f, 0.f, 0.f};
    #pragma unroll 16
    for (int ch = 0; ch < 16; ++ch) {
        uint4 v = srcp[(size_t)ch * 2048];
        const __nv_bfloat162* pv = (const __nv_bfloat162*)&v;
        #pragma unroll
        for (int t2 = 0; t2 < 4; ++t2) {
            float2 f = __bfloat1622float2(pv[t2]);
            s[2 * t2] += f.x; s[2 * t2 + 1] += f.y;
        }
    }
    float4* d = (float4*)(g_wpart + (size_t)rem * 128 + p * 8);
    d[0] = make_float4(s[0], s[1], s[2], s[3]);
    d[1] = make_float4(s[4], s[5], s[6], s[7]);
}

// ---- reduce stage 2 v3: 4 threads per output, shfl combine ----
__global__ void __launch_bounds__(256) k_prep() {
    int u = blockIdx.x * 256 + threadIdx.x;    // 0..32767
    int ef = u >> 3, s = u & 7;
    int jq = s & 1, psub = s >> 1;
    const float4* row = (const float4*)(g_wpart + (size_t)ef * 128);
    float4 a = make_float4(0.f, 0.f, 0.f, 0.f);
    #pragma unroll
    for (int i = 0; i < 4; ++i) {              // p = psub + 4i
        float4 v = row[psub * 2 + jq + i * 8];
        a.x += v.x; a.y += v.y; a.z += v.z; a.w += v.w;
    }
    a.x += __shfl_xor_sync(~0u, a.x, 2); a.y += __shfl_xor_sync(~0u, a.y, 2);
    a.z += __shfl_xor_sync(~0u, a.z, 2); a.w += __shfl_xor_sync(~0u, a.w, 2);
    a.x += __shfl_xor_sync(~0u, a.x, 4); a.y += __shfl_xor_sync(~0u, a.y, 4);
    a.z += __shfl_xor_sync(~0u, a.z, 4); a.w += __shfl_xor_sync(~0u, a.w, 4);
    if (psub == 0) {
        int cls = ef >> 5, quad = ef & 31;
        int nc = ((cls & 63) << 1) | (cls >> 6);
        int k0 = quad * 8;
        int kc = k0 >> 6, uu = (k0 >> 3) & 7;
        __nv_bfloat162* d2 = (__nv_bfloat162*)(g_wbf + kc * 8192
                            + (nc * 8 + (uu ^ (nc & 7))) * 8 + jq * 4);
        d2[0] = __floats2bfloat162_rn(a.x, a.y);
        d2[1] = __floats2bfloat162_rn(a.z, a.w);
    }
    if (u < 3 * NCLS) {
        int which = u >> 6, c2 = u & 63;
        float cs = (float)g_icnt[0][c2], ct = (float)g_icnt[1][c2];
        g_inv[u] = (which == 0) ? 1.f / cs : (which == 1) ? 1.f / ct : 1.f / (cs + ct);
    }
}

// ---- persistent fused GEMM + KL: 296 blocks x 256 thr, W staged once ----
#define WB_OFF 0
#define FB_OFF 65536
#define PM_OFF 98304
#define INV_OFF 110592
#define RED_OFF 111360
#define SMEM_MAIN 111392

__global__ void __launch_bounds__(256, 2) k_main() {
    extern __shared__ unsigned char sm[];
    float* pm    = (float*)(sm + PM_OFF);
    float* inv_s = (float*)(sm + INV_OFF);
    float* red   = (float*)(sm + RED_OFF);
    const uint32_t sb = smem_u32(sm);
    const int tid = threadIdx.x, w = tid >> 5, lane = tid & 31;
    const int g = lane >> 2, t = lane & 3;
    const int wm = w >> 2, wn = w & 3;
    const int b = blockIdx.x;
    const int nt = (b < 136) ? 4 : 3;           // 136*4 + 160*3 = 1024 tiles
    const int totc = nt * 4;

    if (tid < 192) inv_s[tid] = g_inv[tid];

    // W once (group), then first F chunk (group)
    #pragma unroll
    for (int j = 0; j < 16; ++j) {
        int uu = j * 256 + tid;
        cpa16(sb + WB_OFF + uu * 16, g_wbf + uu * 8);
    }
    cp_commit();
    {
        const __nv_bfloat16* fr = g_featbf + (size_t)b * 128 * DIM;
        #pragma unroll
        for (int j = 0; j < 4; ++j) {
            int uu = j * 256 + tid, row = uu >> 3, uq = uu & 7;
            cpa16(sb + FB_OFF + (uint32_t)(row * 8 + (uq ^ (row & 7))) * 16,
                  fr + (size_t)row * DIM + uq * 8);
        }
        cp_commit();
    }

    const float LOG2E = 1.44269504f;
    float invS[4], invT[4], invM[4];
    float acc[4][4][4];
    float Jacc = 0.f;

    #pragma unroll
    for (int x = 0; x < 4; ++x)
        #pragma unroll
        for (int y = 0; y < 4; ++y)
            #pragma unroll
            for (int z = 0; z < 4; ++z) acc[x][y][z] = 0.f;

    for (int c = 0; c < totc; ++c) {
        if (c + 1 < totc) {
            int tl = (c + 1) >> 2, kc = (c + 1) & 3;
            const __nv_bfloat16* fr = g_featbf + (size_t)(b + tl * 296) * 128 * DIM;
            uint32_t slot = sb + FB_OFF + ((c + 1) & 1) * 16384;
            #pragma unroll
            for (int j = 0; j < 4; ++j) {
                int uu = j * 256 + tid, row = uu >> 3, uq = uu & 7;
                cpa16(slot + (uint32_t)(row * 8 + (uq ^ (row & 7))) * 16,
                      fr + (size_t)row * DIM + kc * 64 + uq * 8);
            }
            cp_commit();
            cp_wait<1>();
        } else {
            cp_commit();
            cp_wait<0>();
        }
        __syncthreads();

        const uint32_t fb = sb + FB_OFF + (c & 1) * 16384;
        const uint32_t wb = sb + WB_OFF + (c & 3) * 16384;
        #pragma unroll
        for (int s = 0; s < 4; ++s) {
            uint32_t a[4][4], bb[4][2];
            #pragma unroll
            for (int mt = 0; mt < 4; ++mt) {
                int r0 = wm * 64 + mt * 16 + g, r1 = r0 + 8;
                a[mt][0] = lds_u32(fb + (uint32_t)(r0 * 8 + ((2*s)   ^ (r0 & 7))) * 16 + 4 * t);
                a[mt][1] = lds_u32(fb + (uint32_t)(r1 * 8 + ((2*s)   ^ (r1 & 7))) * 16 + 4 * t);
                a[mt][2] = lds_u32(fb + (uint32_t)(r0 * 8 + ((2*s+1) ^ (r0 & 7))) * 16 + 4 * t);
                a[mt][3] = lds_u32(fb + (uint32_t)(r1 * 8 + ((2*s+1) ^ (r1 & 7))) * 16 + 4 * t);
            }
            #pragma unroll
            for (int ntv = 0; ntv < 4; ++ntv) {
                int cn = wn * 32 + ntv * 8 + g;
                bb[ntv][0] = lds_u32(wb + (uint32_t)(cn * 8 + ((2*s)   ^ (cn & 7))) * 16 + 4 * t);
                bb[ntv][1] = lds_u32(wb + (uint32_t)(cn * 8 + ((2*s+1) ^ (cn & 7))) * 16 + 4 * t);
            }
            #pragma unroll
            for (int mt = 0; mt < 4; ++mt)
                #pragma unroll
                for (int ntv = 0; ntv < 4; ++ntv)
                    mma_bf16(acc[mt][ntv], a[mt], bb[ntv]);
        }
        __syncthreads();

        if ((c & 3) == 3) {
            // epilogue for finished tile (next tile's chunk0 already in flight)
            #pragma unroll
            for (int ntv = 0; ntv < 4; ++ntv) {
                int cc = wn * 16 + ntv * 4 + t;
                invS[ntv] = inv_s[cc] * LOG2E;
                invT[ntv] = inv_s[64 + cc] * LOG2E;
                invM[ntv] = inv_s[128 + cc] * LOG2E;
            }
            #pragma unroll
            for (int mt = 0; mt < 4; ++mt) {
                #pragma unroll
                for (int h = 0; h < 2; ++h) {
                    float Z0 = 0.f, Z1 = 0.f, Z2 = 0.f;
                    float B0 = 0.f, B1 = 0.f, B2 = 0.f;
                    #pragma unroll
                    for (int ntv = 0; ntv < 4; ++ntv) {
                        float Sr = acc[mt][ntv][2*h], Tr = acc[mt][ntv][2*h+1];
                        float ps2 = Sr * invS[ntv], pt = Tr * invT[ntv],
                              pv = (Sr + Tr) * invM[ntv];
                        float eS = ex2(ps2), eT = ex2(pt), eM = ex2(pv);
                        float dw = ps2 - pt, dx = ps2 - pv, dy = pt - pv;
                        Z0 += eS; Z1 += eT; Z2 += eM;
                        B0 += eS * (dw + dx);
                        B1 += eT * (dy - dw);
                        B2 -= eM * (dx + dy);
                    }
                    Z0 = qsum(Z0); Z1 = qsum(Z1); Z2 = qsum(Z2);
                    B0 = qsum(B0); B1 = qsum(B1); B2 = qsum(B2);
                    if (t == 0) {
                        int row = wm * 64 + mt * 16 + g + 8 * h;
                        float* d = pm + (row * 4 + wn) * 6;
                        d[0] = Z0; d[1] = Z1; d[2] = Z2;
                        d[3] = B0; d[4] = B1; d[5] = B2;
                    }
                }
            }
            __syncthreads();
            if (tid < 128) {
                float v[6];
                #pragma unroll
                for (int i = 0; i < 6; ++i)
                    v[i] = pm[(tid * 4 + 0) * 6 + i] + pm[(tid * 4 + 1) * 6 + i]
                         + pm[(tid * 4 + 2) * 6 + i] + pm[(tid * 4 + 3) * 6 + i];
                Jacc += (__fdividef(v[3], v[0]) + __fdividef(v[4], v[1])
                       + __fdividef(v[5], v[2])) * 0.69314718f;
            }
            #pragma unroll
            for (int x = 0; x < 4; ++x)
                #pragma unroll
                for (int y = 0; y < 4; ++y)
                    #pragma unroll
                    for (int z = 0; z < 4; ++z) acc[x][y][z] = 0.f;
        }
    }

    #pragma unroll
    for (int o = 16; o; o >>= 1) Jacc += __shfl_xor_sync(~0u, Jacc, o);
    if (lane == 0) red[w] = Jacc;
    __syncthreads();
    if (tid == 0) {
        float bs = 0.f;
        #pragma unroll
        for (int i = 0; i < 8; ++i) bs += red[i];
        atomicAdd(&g_acc, (double)bs);
    }
}

__global__ void k_final(float* out) {
    out[0] = (float)(g_acc * (0.5 / (3.0 * 131072.0 * 64.0)));
}

extern "C" void kernel_launch(void* const* d_in, const int* in_sizes, int n_in,
                              void* d_out, int out_size) {
    const float* src = (const float*)d_in[0];
    const float* trg = (const float*)d_in[1];
    const int*   sl  = (const int*)d_in[2];
    const int*   tl  = (const int*)d_in[3];

    cudaFuncSetAttribute(k_segsum, cudaFuncAttributeMaxDynamicSharedMemorySize, 106496);
    cudaFuncSetAttribute(k_main,   cudaFuncAttributeMaxDynamicSharedMemorySize, SMEM_MAIN);

    k_zero<<<1, 256>>>(sl);
    k_segsum<<<512, 128, 106496>>>(src, trg, sl, tl);
    k_red<<<256, 256>>>();
    k_prep<<<128, 256>>>();
    k_main<<<296, 256, SMEM_MAIN>>>();
    k_final<<<1, 1>>>((float*)d_out);
}